// round 13
// baseline (speedup 1.0000x reference)
#include <cuda_runtime.h>
#include <cuda_fp16.h>

#define B_ 4
#define C_ 256
#define N_ 2048
#define H_ 8
#define D_ 32

// Scratch (allocation-free rule: __device__ globals)
__device__ float g_Y[B_*C_*N_];      // proj + bias + residual, [B,C,N]
__device__ __half g_Qb[B_*C_*N_];    // [bh][n][d] fp16, pre-scaled by D^-0.5*log2e
__device__ __half g_Kb[B_*C_*N_];    // [bh][n][d] fp16
__device__ __half g_Vb[B_*C_*N_];    // [bh][d][n] fp16
__device__ __half g_Xh[B_*N_*C_];    // x transposed [b][n][c] fp16 hi/lo
__device__ __half g_Xl[B_*N_*C_];
__device__ __half g_AOh[B_*N_*C_];   // attention out [b][n][c] fp16 hi/lo
__device__ __half g_AOl[B_*N_*C_];
__device__ __half g_Wqh[3*C_*C_];    // QKV weights: fp16 hi only (2-term GEMM)
__device__ __half g_Wph[C_*C_];      // proj weights: fp16 hi only (2-term GEMM)

// fp16 inputs, fp32 accumulator
__device__ __forceinline__ void mma_f16(float* d, unsigned a0, unsigned a1,
                                        unsigned a2, unsigned a3,
                                        unsigned b0, unsigned b1) {
    asm volatile(
        "mma.sync.aligned.m16n8k16.row.col.f32.f16.f16.f32 "
        "{%0,%1,%2,%3}, {%4,%5,%6,%7}, {%8,%9}, {%0,%1,%2,%3};\n"
        : "+f"(d[0]), "+f"(d[1]), "+f"(d[2]), "+f"(d[3])
        : "r"(a0), "r"(a1), "r"(a2), "r"(a3), "r"(b0), "r"(b1));
}

// fp16 inputs, fp16 accumulator; D packed {c0,c1},{c2,c3}
__device__ __forceinline__ void mma_f16acc(unsigned& d0, unsigned& d1,
                                           unsigned a0, unsigned a1,
                                           unsigned a2, unsigned a3,
                                           unsigned b0, unsigned b1) {
    asm volatile(
        "mma.sync.aligned.m16n8k16.row.col.f16.f16.f16.f16 "
        "{%0,%1}, {%2,%3,%4,%5}, {%6,%7}, {%0,%1};\n"
        : "+r"(d0), "+r"(d1)
        : "r"(a0), "r"(a1), "r"(a2), "r"(a3), "r"(b0), "r"(b1));
}

__device__ __forceinline__ void ldmatrix_x4(unsigned& r0, unsigned& r1,
                                            unsigned& r2, unsigned& r3,
                                            unsigned addr) {
    asm volatile("ldmatrix.sync.aligned.m8n8.x4.shared.b16 {%0,%1,%2,%3}, [%4];"
                 : "=r"(r0), "=r"(r1), "=r"(r2), "=r"(r3) : "r"(addr));
}

__device__ __forceinline__ void cp_async16(unsigned dst, const void* src) {
    asm volatile("cp.async.cg.shared.global [%0], [%1], 16;"
                 :: "r"(dst), "l"(src));
}
__device__ __forceinline__ unsigned pack_f16x2(__half a, __half b) {
    unsigned short ua = *(unsigned short*)&a;
    unsigned short ub = *(unsigned short*)&b;
    return (unsigned)ua | ((unsigned)ub << 16);
}
// packs {lo, hi} into f16x2 (lo -> lower 16 bits)
__device__ __forceinline__ unsigned cvt_f16x2(float hi, float lo) {
    unsigned r;
    asm("cvt.rn.f16x2.f32 %0, %1, %2;" : "=r"(r) : "f"(hi), "f"(lo));
    return r;
}
// elementwise 2^x on an f16x2 pair
__device__ __forceinline__ unsigned ex2_f16x2(unsigned x) {
    unsigned r;
    asm("ex2.approx.f16x2 %0, %1;" : "=r"(r) : "r"(x));
    return r;
}

// ---------------------------------------------------------------------------
// Prep 1: weights -> fp16 hi only (both GEMMs are 2-term).
// ---------------------------------------------------------------------------
#define WQ_SZ (3*C_*C_)
#define WP_SZ (C_*C_)
__global__ __launch_bounds__(256) void prep_w_kernel(
    const float* __restrict__ w_qkv, const float* __restrict__ w_proj)
{
    int i = blockIdx.x * 256 + threadIdx.x;
    if (i < WQ_SZ) g_Wqh[i] = __float2half_rn(w_qkv[i]);
    else           g_Wph[i - WQ_SZ] = __float2half_rn(w_proj[i - WQ_SZ]);
}

// ---------------------------------------------------------------------------
// Prep 2: transpose + split x: [b][c][n] fp32 -> [b][n][c] fp16 hi/lo.
// ---------------------------------------------------------------------------
__global__ __launch_bounds__(256) void prep_x_kernel(const float* __restrict__ x)
{
    __shared__ float ts[32][132];
    const int b  = blockIdx.z;
    const int c0 = blockIdx.y * 32;
    const int n0 = blockIdx.x * 128;
    const int t  = threadIdx.x;

    {
        int cc = t >> 3, nseg = t & 7;
        const float* src = x + b * (C_ * N_) + (c0 + cc) * N_ + n0 + nseg * 16;
        #pragma unroll
        for (int j = 0; j < 4; j++) {
            float4 v = *(const float4*)(src + j * 4);
            int nn = nseg * 16 + j * 4;
            ts[cc][nn] = v.x; ts[cc][nn+1] = v.y; ts[cc][nn+2] = v.z; ts[cc][nn+3] = v.w;
        }
    }
    __syncthreads();
    {
        int nn = t & 127, arr = t >> 7;
        unsigned w[16];
        #pragma unroll
        for (int cc = 0; cc < 32; cc += 2) {
            float v0 = ts[cc][nn], v1 = ts[cc+1][nn];
            __half h0 = __float2half_rn(v0);
            __half h1 = __float2half_rn(v1);
            if (arr) {
                h0 = __float2half_rn(v0 - __half2float(h0));
                h1 = __float2half_rn(v1 - __half2float(h1));
            }
            w[cc >> 1] = pack_f16x2(h0, h1);
        }
        __half* dst = (arr ? g_Xl : g_Xh) + b * (N_ * C_) + (size_t)(n0 + nn) * C_ + c0;
        uint4* d4 = (uint4*)dst;
        #pragma unroll
        for (int j = 0; j < 4; j++)
            d4[j] = make_uint4(w[j*4], w[j*4+1], w[j*4+2], w[j*4+3]);
    }
}

// ---------------------------------------------------------------------------
// fp16 GEMM (2-term: Ah*Bh + Ah*Bl): CTA 128x64, BK=32, double-buffered
// cp.async, ldmatrix frags.
// MODE 0 (QKV): fp16 Q/K [bh][n][d], V [bh][d][n].
// MODE 1 (proj): + bias + residual -> g_Y fp32.
// ---------------------------------------------------------------------------
template <int MODE>
__global__ __launch_bounds__(256) void gemm_f16_kernel(
    const __half* __restrict__ Agh,
    const __half* __restrict__ Bgh, const __half* __restrict__ Bgl,
    const float* __restrict__ bias, const float* __restrict__ x)
{
    constexpr int S_AH = 0;
    constexpr int S_BH = 5120;
    constexpr int S_BL = 7680;
    constexpr int STAGE = 10240;

    extern __shared__ __half smh[];
    const unsigned smem_base = (unsigned)__cvta_generic_to_shared(smh);

    const int b  = blockIdx.z;
    const int o0 = blockIdx.y * 128;
    const int n0 = blockIdx.x * 64;
    const int tid  = threadIdx.x;
    const int warp = tid >> 5;
    const int lane = tid & 31;
    const int g = lane >> 2;
    const int q = lane & 3;
    const int wm = (warp >> 1) * 32;
    const int wn = (warp & 1) * 32;
    const int arow  = lane & 15;
    const int acol8 = (lane >> 4) * 8;
    const int brow  = lane & 7;
    const int bcol8 = (lane >> 3) * 8;

    const __half* bgh = Bgh + (size_t)b * (N_ * C_);
    const __half* bgl = Bgl + (size_t)b * (N_ * C_);

    float acc[2][4][4] = {};

    auto load_tile = [&](int kt, int s) {
        const int kk = kt * 32;
        const unsigned sb = smem_base + s * (STAGE * 2);
        #pragma unroll
        for (int i = 0; i < 2; i++) {
            int c = tid + i * 256;
            int m = c >> 2, ck = c & 3;
            const __half* src = Agh + (o0 + m) * C_ + kk + ck * 8;
            unsigned dst = sb + S_AH * 2 + (m * 40 + ck * 8) * 2;
            cp_async16(dst, src);
        }
        #pragma unroll
        for (int i = 0; i < 2; i++) {
            int idx = tid + i * 256;
            int arr = idx >> 8;
            int c   = idx & 255;
            int n = c >> 2, ck = c & 3;
            const __half* src = (arr ? bgl : bgh) + (size_t)(n0 + n) * C_ + kk + ck * 8;
            unsigned dst = sb + (arr ? S_BL : S_BH) * 2 + (n * 40 + ck * 8) * 2;
            cp_async16(dst, src);
        }
        asm volatile("cp.async.commit_group;" ::: "memory");
    };

    load_tile(0, 0);

    const int NKT = C_ / 32;
    for (int kt = 0; kt < NKT; kt++) {
        if (kt + 1 < NKT) {
            load_tile(kt + 1, (kt + 1) & 1);
            asm volatile("cp.async.wait_group 1;" ::: "memory");
        } else {
            asm volatile("cp.async.wait_group 0;" ::: "memory");
        }
        __syncthreads();

        const unsigned sb = smem_base + (kt & 1) * (STAGE * 2);

        unsigned bhf[4][4], blf[4][4];
        #pragma unroll
        for (int ni = 0; ni < 4; ni++) {
            unsigned off = ((wn + ni * 8 + brow) * 40 + bcol8) * 2;
            ldmatrix_x4(bhf[ni][0], bhf[ni][1], bhf[ni][2], bhf[ni][3],
                        sb + S_BH * 2 + off);
            ldmatrix_x4(blf[ni][0], blf[ni][1], blf[ni][2], blf[ni][3],
                        sb + S_BL * 2 + off);
        }

        #pragma unroll
        for (int kb = 0; kb < 2; kb++) {
            unsigned ah[2][4];
            #pragma unroll
            for (int mi = 0; mi < 2; mi++) {
                unsigned off = ((wm + mi * 16 + arow) * 40 + kb * 16 + acol8) * 2;
                ldmatrix_x4(ah[mi][0], ah[mi][1], ah[mi][2], ah[mi][3],
                            sb + S_AH * 2 + off);
            }
            #pragma unroll
            for (int ni = 0; ni < 4; ni++) {
                unsigned b0h = bhf[ni][2*kb], b1h = bhf[ni][2*kb+1];
                unsigned b0l = blf[ni][2*kb], b1l = blf[ni][2*kb+1];
                #pragma unroll
                for (int mi = 0; mi < 2; mi++) {
                    mma_f16(acc[mi][ni], ah[mi][0], ah[mi][1], ah[mi][2], ah[mi][3], b0h, b1h);
                    mma_f16(acc[mi][ni], ah[mi][0], ah[mi][1], ah[mi][2], ah[mi][3], b0l, b1l);
                }
            }
        }
        __syncthreads();
    }

    if (MODE == 0) {
        const int s = o0 >> 8;                      // 0=q, 1=k, 2=v
        const float scale = (s == 0)
            ? 0.17677669529663687f * 1.4426950408889634f : 1.0f;
        if (s == 2) {
            #pragma unroll
            for (int mi = 0; mi < 2; mi++) {
                int o = o0 + wm + mi * 16 + g;
                float bv0 = bias[o], bv1 = bias[o + 8];
                int cd0 = o & 255, cd1 = (o + 8) & 255;
                #pragma unroll
                for (int ni = 0; ni < 4; ni++) {
                    int col = n0 + wn + ni * 8 + 2 * q;
                    unsigned p0 = cvt_f16x2(acc[mi][ni][1] + bv0, acc[mi][ni][0] + bv0);
                    unsigned p1 = cvt_f16x2(acc[mi][ni][3] + bv1, acc[mi][ni][2] + bv1);
                    *(unsigned*)&g_Vb[(size_t)(b * 256 + cd0) * N_ + col] = p0;
                    *(unsigned*)&g_Vb[(size_t)(b * 256 + cd1) * N_ + col] = p1;
                }
            }
        } else {
            float* Ts = (float*)smh;
            #pragma unroll
            for (int mi = 0; mi < 2; mi++) {
                int r0 = wm + mi * 16 + g;
                int o  = o0 + r0;
                float bv0 = bias[o], bv1 = bias[o + 8];
                #pragma unroll
                for (int ni = 0; ni < 4; ni++) {
                    int cl = wn + ni * 8 + 2 * q;
                    Ts[cl * 133 + r0]           = (acc[mi][ni][0] + bv0) * scale;
                    Ts[(cl + 1) * 133 + r0]     = (acc[mi][ni][1] + bv0) * scale;
                    Ts[cl * 133 + r0 + 8]       = (acc[mi][ni][2] + bv1) * scale;
                    Ts[(cl + 1) * 133 + r0 + 8] = (acc[mi][ni][3] + bv1) * scale;
                }
            }
            __syncthreads();
            int nl = tid & 63, hh = tid >> 6;
            int h0 = (o0 & 255) >> 5;
            int bh = b * 8 + h0 + hh;
            unsigned w[16];
            const float* row = Ts + nl * 133 + hh * 32;
            #pragma unroll
            for (int dd = 0; dd < 32; dd += 2)
                w[dd >> 1] = cvt_f16x2(row[dd + 1], row[dd]);
            __half* dst = (s == 0 ? g_Qb : g_Kb) + ((size_t)bh * N_ + n0 + nl) * 32;
            uint4* d4 = (uint4*)dst;
            #pragma unroll
            for (int j = 0; j < 4; j++)
                d4[j] = make_uint4(w[j*4], w[j*4+1], w[j*4+2], w[j*4+3]);
        }
    } else {
        const float* xb = x + b * (C_ * N_);
        float* yb = g_Y + b * (C_ * N_);
        #pragma unroll
        for (int mi = 0; mi < 2; mi++) {
            int o = o0 + wm + mi * 16 + g;
            float bv0 = bias[o], bv1 = bias[o + 8];
            #pragma unroll
            for (int ni = 0; ni < 4; ni++) {
                int col = n0 + wn + ni * 8 + 2 * q;
                float2 x0 = *(const float2*)&xb[o * N_ + col];
                float2 x1 = *(const float2*)&xb[(o + 8) * N_ + col];
                float2 v0, v1;
                v0.x = acc[mi][ni][0] + bv0 + x0.x;
                v0.y = acc[mi][ni][1] + bv0 + x0.y;
                v1.x = acc[mi][ni][2] + bv1 + x1.x;
                v1.y = acc[mi][ni][3] + bv1 + x1.y;
                *(float2*)&yb[o * N_ + col] = v0;
                *(float2*)&yb[(o + 8) * N_ + col] = v1;
            }
        }
    }
}

// ---------------------------------------------------------------------------
// Flash attention, fp16. CTA = 128 queries of one (b,h), 8 warps x 16 rows
// (256 threads): K/V staged once per 128 queries (half the smem traffic of
// the 64-query variant) at ~24 warps/SM. QK on f16-accum mma; packed
// D-fragments feed ex2.approx.f16x2 directly; results are PV A-fragments.
// 3-stage cp.async pipeline, one barrier per tile. No running max.
// ---------------------------------------------------------------------------
#define AQ_H 5120                          // Qs[128][40]
#define STG_H 4864                         // 2560 (Ks[64][40]) + 2304 (Vt[32][72])
#define ATTN_SMEM_H (AQ_H + 3*STG_H)       // 19712 halves = 39424 B
#define ONES_F16X2 0x3C003C00u

__global__ __launch_bounds__(256) void attn_kernel()
{
    extern __shared__ __half smh[];
    const unsigned smem_base = (unsigned)__cvta_generic_to_shared(smh);

    const int bh   = blockIdx.y;
    const int n0   = blockIdx.x * 128;
    const int tid  = threadIdx.x;
    const int warp = tid >> 5;
    const int lane = tid & 31;
    const int g    = lane >> 2;
    const int q    = lane & 3;
    const int lrow = lane & 7;
    const int lcol8 = (lane >> 3) * 8;

    const __half* Qg = g_Qb + (size_t)bh * N_ * 32;
    const __half* Kg = g_Kb + (size_t)bh * N_ * 32;
    const __half* Vg = g_Vb + (size_t)bh * 32 * N_;

    auto load_kv = [&](int t, int s) {
        const unsigned sb = smem_base + (AQ_H + s * STG_H) * 2;
        {
            int j = tid >> 2, off = (tid & 3) * 8;
            cp_async16(sb + (j * 40 + off) * 2, Kg + (size_t)(t + j) * 32 + off);
        }
        {
            int dd = tid >> 3, joff = (tid & 7) * 8;
            cp_async16(sb + (2560 + dd * 72 + joff) * 2, Vg + (size_t)dd * N_ + t + joff);
        }
        asm volatile("cp.async.commit_group;" ::: "memory");
    };

    // Prologue: Q tile (128x32) + stages 0,1
    #pragma unroll
    for (int i = 0; i < 2; i++) {
        int c = tid + i * 256;
        int n = c >> 2, off = (c & 3) * 8;
        cp_async16(smem_base + (n * 40 + off) * 2, Qg + (size_t)(n0 + n) * 32 + off);
    }
    load_kv(0, 0);
    load_kv(64, 1);
    asm volatile("cp.async.wait_group 1;" ::: "memory");
    __syncthreads();

    // Q A-fragments: rows warp*16 + arow, cols kb*16 + acol8
    unsigned qa[2][4];
    {
        int arow = lane & 15, acol8q = (lane >> 4) * 8;
        #pragma unroll
        for (int kb = 0; kb < 2; kb++) {
            unsigned off = ((warp * 16 + arow) * 40 + kb * 16 + acol8q) * 2;
            ldmatrix_x4(qa[kb][0], qa[kb][1], qa[kb][2], qa[kb][3],
                        smem_base + off);
        }
    }

    float o[4][4] = {};
    float lac[4] = {};

    const int NT = N_ / 64;  // 32
    int st = 0, ldst = 2;
    for (int t = 0; t < NT; t++) {
        if (t + 1 < NT) {
            asm volatile("cp.async.wait_group 1;" ::: "memory");
        } else {
            asm volatile("cp.async.wait_group 0;" ::: "memory");
        }
        __syncthreads();
        if (t + 2 < NT) load_kv((t + 2) * 64, ldst);

        const unsigned ks_u32 = smem_base + (AQ_H + st * STG_H) * 2;
        const unsigned vt_u32 = ks_u32 + 2560 * 2;

        // S = Q K^T on f16-accum mma
        unsigned su[8][2] = {};
        #pragma unroll
        for (int ni = 0; ni < 8; ni++) {
            unsigned kf0, kf1, kf2, kf3;
            ldmatrix_x4(kf0, kf1, kf2, kf3,
                        ks_u32 + ((ni * 8 + lrow) * 40 + lcol8) * 2);
            mma_f16acc(su[ni][0], su[ni][1],
                       qa[0][0], qa[0][1], qa[0][2], qa[0][3], kf0, kf1);
            mma_f16acc(su[ni][0], su[ni][1],
                       qa[1][0], qa[1][1], qa[1][2], qa[1][3], kf2, kf3);
        }

        // p = 2^s
        unsigned pu[8][2];
        #pragma unroll
        for (int ni = 0; ni < 8; ni++) {
            pu[ni][0] = ex2_f16x2(su[ni][0]);
            pu[ni][1] = ex2_f16x2(su[ni][1]);
        }

        // O += P V
        #pragma unroll
        for (int ni = 0; ni < 4; ni++) {
            unsigned vf[8];
            unsigned va = vt_u32 + ((ni * 8 + lrow) * 72 + lcol8) * 2;
            ldmatrix_x4(vf[0], vf[1], vf[2], vf[3], va);
            ldmatrix_x4(vf[4], vf[5], vf[6], vf[7], va + 64);
            #pragma unroll
            for (int kj = 0; kj < 4; kj++) {
                mma_f16(o[ni],
                        pu[2*kj][0], pu[2*kj][1],
                        pu[2*kj+1][0], pu[2*kj+1][1],
                        vf[2*kj], vf[2*kj+1]);
            }
        }
        // l += P * ones
        #pragma unroll
        for (int kj = 0; kj < 4; kj++) {
            mma_f16(lac,
                    pu[2*kj][0], pu[2*kj][1],
                    pu[2*kj+1][0], pu[2*kj+1][1],
                    ONES_F16X2, ONES_F16X2);
        }

        if (++st == 3) st = 0;
        if (++ldst == 3) ldst = 0;
    }

    float linv0 = 1.f / lac[0];   // row warp*16 + g
    float linv1 = 1.f / lac[2];   // row warp*16 + g + 8

    __syncthreads();
    float* Os = (float*)smh;  // [128][33]
    {
        int r = warp * 16 + g;
        #pragma unroll
        for (int ni = 0; ni < 4; ni++) {
            int dcol = ni * 8 + 2 * q;
            Os[r * 33 + dcol]           = o[ni][0] * linv0;
            Os[r * 33 + dcol + 1]       = o[ni][1] * linv0;
            Os[(r + 8) * 33 + dcol]     = o[ni][2] * linv1;
            Os[(r + 8) * 33 + dcol + 1] = o[ni][3] * linv1;
        }
    }
    __syncthreads();
    {
        int b = bh >> 3, h = bh & 7;
        int row = tid & 127, half = tid >> 7;   // half: d 0-15 or 16-31
        unsigned hw[8], lw[8];
        const float* src = Os + row * 33 + half * 16;
        #pragma unroll
        for (int dd = 0; dd < 16; dd += 2) {
            float v0 = src[dd];
            float v1 = src[dd + 1];
            __half h0 = __float2half_rn(v0);
            __half h1 = __float2half_rn(v1);
            __half l0 = __float2half_rn(v0 - __half2float(h0));
            __half l1 = __float2half_rn(v1 - __half2float(h1));
            hw[dd >> 1] = pack_f16x2(h0, h1);
            lw[dd >> 1] = pack_f16x2(l0, l1);
        }
        size_t base = (size_t)b * (N_ * C_) + (size_t)(n0 + row) * C_ + h * 32 + half * 16;
        uint4* dh = (uint4*)(g_AOh + base);
        uint4* dl = (uint4*)(g_AOl + base);
        dh[0] = make_uint4(hw[0], hw[1], hw[2], hw[3]);
        dh[1] = make_uint4(hw[4], hw[5], hw[6], hw[7]);
        dl[0] = make_uint4(lw[0], lw[1], lw[2], lw[3]);
        dl[1] = make_uint4(lw[4], lw[5], lw[6], lw[7]);
    }
}

// ---------------------------------------------------------------------------
// LayerNorm over channels, float4-vectorized along n.
// Block 256 = 32 n-groups (4 cols each) x 8 c-groups. Grid (N/128, B).
// ---------------------------------------------------------------------------
__global__ __launch_bounds__(256) void ln_kernel(
    const float* __restrict__ ln_g, const float* __restrict__ ln_b,
    float* __restrict__ out)
{
    __shared__ float4 ssum[8][32], ssq[8][32];
    __shared__ float4 smu[32], srstd[32];

    const int batch = blockIdx.y;
    const int nc = threadIdx.x & 31;
    const int cg = threadIdx.x >> 5;
    const int n4 = blockIdx.x * 128 + nc * 4;
    const float* Yb = g_Y + batch * (C_ * N_) + n4;

    float4 sum = make_float4(0.f, 0.f, 0.f, 0.f);
    float4 sq  = make_float4(0.f, 0.f, 0.f, 0.f);
    #pragma unroll 8
    for (int i = 0; i < 32; i++) {
        float4 v = *(const float4*)&Yb[(cg * 32 + i) * N_];
        sum.x += v.x; sum.y += v.y; sum.z += v.z; sum.w += v.w;
        sq.x += v.x * v.x; sq.y += v.y * v.y; sq.z += v.z * v.z; sq.w += v.w * v.w;
    }
    ssum[cg][nc] = sum; ssq[cg][nc] = sq;
    __syncthreads();
    if (cg == 0) {
        float4 s = make_float4(0.f, 0.f, 0.f, 0.f);
        float4 qq = make_float4(0.f, 0.f, 0.f, 0.f);
        #pragma unroll
        for (int j = 0; j < 8; j++) {
            float4 a = ssum[j][nc], bq = ssq[j][nc];
            s.x += a.x; s.y += a.y; s.z += a.z; s.w += a.w;
            qq.x += bq.x; qq.y += bq.y; qq.z += bq.z; qq.w += bq.w;
        }
        float4 mu, rs;
        mu.x = s.x * (1.f / C_); mu.y = s.y * (1.f / C_);
        mu.z = s.z * (1.f / C_); mu.w = s.w * (1.f / C_);
        rs.x = rsqrtf(qq.x * (1.f / C_) - mu.x * mu.x + 1e-5f);
        rs.y = rsqrtf(qq.y * (1.f / C_) - mu.y * mu.y + 1e-5f);
        rs.z = rsqrtf(qq.z * (1.f / C_) - mu.z * mu.z + 1e-5f);
        rs.w = rsqrtf(qq.w * (1.f / C_) - mu.w * mu.w + 1e-5f);
        smu[nc] = mu; srstd[nc] = rs;
    }
    __syncthreads();
    float4 mu = smu[nc], rs = srstd[nc];
    float* ob = out + batch * (C_ * N_) + n4;
    #pragma unroll 8
    for (int i = 0; i < 32; i++) {
        int c = cg * 32 + i;
        float4 v = *(const float4*)&Yb[c * N_];
        float gg = ln_g[c], bb = ln_b[c];
        float4 r;
        r.x = (v.x - mu.x) * rs.x * gg + bb;
        r.y = (v.y - mu.y) * rs.y * gg + bb;
        r.z = (v.z - mu.z) * rs.z * gg + bb;
        r.w = (v.w - mu.w) * rs.w * gg + bb;
        *(float4*)&ob[c * N_] = r;
    }
}

// ---------------------------------------------------------------------------
extern "C" void kernel_launch(void* const* d_in, const int* in_sizes, int n_in,
                              void* d_out, int out_size)
{
    const float* x      = (const float*)d_in[0];
    const float* w_qkv  = (const float*)d_in[1];
    const float* b_qkv  = (const float*)d_in[2];
    const float* w_proj = (const float*)d_in[3];
    const float* b_proj = (const float*)d_in[4];
    const float* ln_g   = (const float*)d_in[5];
    const float* ln_b   = (const float*)d_in[6];
    float* out = (float*)d_out;

    const int gemm_smem = 2 * 10240 * 2;    // 40960 B
    const int attn_smem = ATTN_SMEM_H * 2;  // 39424 B
    cudaFuncSetAttribute(gemm_f16_kernel<0>,
                         cudaFuncAttributeMaxDynamicSharedMemorySize, gemm_smem);
    cudaFuncSetAttribute(gemm_f16_kernel<1>,
                         cudaFuncAttributeMaxDynamicSharedMemorySize, gemm_smem);
    cudaFuncSetAttribute(attn_kernel,
                         cudaFuncAttributeMaxDynamicSharedMemorySize, attn_smem);

    __half *p_Wqh, *p_Wph, *p_Xh, *p_Xl, *p_AOh, *p_AOl;
    cudaGetSymbolAddress((void**)&p_Wqh, g_Wqh);
    cudaGetSymbolAddress((void**)&p_Wph, g_Wph);
    cudaGetSymbolAddress((void**)&p_Xh,  g_Xh);
    cudaGetSymbolAddress((void**)&p_Xl,  g_Xl);
    cudaGetSymbolAddress((void**)&p_AOh, g_AOh);
    cudaGetSymbolAddress((void**)&p_AOl, g_AOl);

    prep_w_kernel<<<(WQ_SZ + WP_SZ) / 256, 256>>>(w_qkv, w_proj);
    prep_x_kernel<<<dim3(N_ / 128, C_ / 32, B_), 256>>>(x);
    gemm_f16_kernel<0><<<dim3(N_ / 64, (3 * C_) / 128, B_), 256, gemm_smem>>>(
        p_Wqh, p_Xh, p_Xl, b_qkv, nullptr);
    attn_kernel<<<dim3(N_ / 128, B_ * H_), 256, attn_smem>>>();
    gemm_f16_kernel<1><<<dim3(N_ / 64, C_ / 128, B_), 256, gemm_smem>>>(
        p_Wph, p_AOh, p_AOl, b_proj, x);
    ln_kernel<<<dim3(N_ / 128, B_), 256>>>(ln_g, ln_b, out);
}

// round 14
// speedup vs baseline: 1.1154x; 1.1154x over previous
#include <cuda_runtime.h>
#include <cuda_fp16.h>

#define B_ 4
#define C_ 256
#define N_ 2048
#define H_ 8
#define D_ 32

// Scratch (allocation-free rule: __device__ globals)
__device__ float g_Y[B_*C_*N_];      // proj + bias + residual, [B,C,N]
__device__ __half g_Qb[B_*C_*N_];    // [bh][n][d] fp16, pre-scaled by D^-0.5*log2e
__device__ __half g_Kb[B_*C_*N_];    // [bh][n][d] fp16
__device__ __half g_Vb[B_*C_*N_];    // [bh][d][n] fp16
__device__ __half g_Xh[B_*N_*C_];    // x transposed [b][n][c] fp16 hi/lo
__device__ __half g_Xl[B_*N_*C_];
__device__ __half g_AOh[B_*N_*C_];   // attention out [b][n][c] fp16 hi/lo
__device__ __half g_AOl[B_*N_*C_];
__device__ __half g_Wqh[3*C_*C_];    // QKV weights: fp16 hi only (2-term GEMM)
__device__ __half g_Wph[C_*C_];      // proj weights: fp16 hi only (2-term GEMM)

// fp16 inputs, fp32 accumulator
__device__ __forceinline__ void mma_f16(float* d, unsigned a0, unsigned a1,
                                        unsigned a2, unsigned a3,
                                        unsigned b0, unsigned b1) {
    asm volatile(
        "mma.sync.aligned.m16n8k16.row.col.f32.f16.f16.f32 "
        "{%0,%1,%2,%3}, {%4,%5,%6,%7}, {%8,%9}, {%0,%1,%2,%3};\n"
        : "+f"(d[0]), "+f"(d[1]), "+f"(d[2]), "+f"(d[3])
        : "r"(a0), "r"(a1), "r"(a2), "r"(a3), "r"(b0), "r"(b1));
}

// fp16 inputs, fp16 accumulator; D packed {c0,c1},{c2,c3}
__device__ __forceinline__ void mma_f16acc(unsigned& d0, unsigned& d1,
                                           unsigned a0, unsigned a1,
                                           unsigned a2, unsigned a3,
                                           unsigned b0, unsigned b1) {
    asm volatile(
        "mma.sync.aligned.m16n8k16.row.col.f16.f16.f16.f16 "
        "{%0,%1}, {%2,%3,%4,%5}, {%6,%7}, {%0,%1};\n"
        : "+r"(d0), "+r"(d1)
        : "r"(a0), "r"(a1), "r"(a2), "r"(a3), "r"(b0), "r"(b1));
}

__device__ __forceinline__ void ldmatrix_x4(unsigned& r0, unsigned& r1,
                                            unsigned& r2, unsigned& r3,
                                            unsigned addr) {
    asm volatile("ldmatrix.sync.aligned.m8n8.x4.shared.b16 {%0,%1,%2,%3}, [%4];"
                 : "=r"(r0), "=r"(r1), "=r"(r2), "=r"(r3) : "r"(addr));
}

__device__ __forceinline__ void cp_async16(unsigned dst, const void* src) {
    asm volatile("cp.async.cg.shared.global [%0], [%1], 16;"
                 :: "r"(dst), "l"(src));
}
__device__ __forceinline__ unsigned pack_f16x2(__half a, __half b) {
    unsigned short ua = *(unsigned short*)&a;
    unsigned short ub = *(unsigned short*)&b;
    return (unsigned)ua | ((unsigned)ub << 16);
}
// packs {lo, hi} into f16x2 (lo -> lower 16 bits)
__device__ __forceinline__ unsigned cvt_f16x2(float hi, float lo) {
    unsigned r;
    asm("cvt.rn.f16x2.f32 %0, %1, %2;" : "=r"(r) : "f"(hi), "f"(lo));
    return r;
}
// elementwise 2^x on an f16x2 pair
__device__ __forceinline__ unsigned ex2_f16x2(unsigned x) {
    unsigned r;
    asm("ex2.approx.f16x2 %0, %1;" : "=r"(r) : "r"(x));
    return r;
}
// elementwise f16x2 add
__device__ __forceinline__ unsigned hadd2(unsigned a, unsigned b) {
    unsigned r;
    asm("add.rn.f16x2 %0, %1, %2;" : "=r"(r) : "r"(a), "r"(b));
    return r;
}

// ---------------------------------------------------------------------------
// Prep 1: weights -> fp16 hi only (both GEMMs are 2-term).
// ---------------------------------------------------------------------------
#define WQ_SZ (3*C_*C_)
#define WP_SZ (C_*C_)
__global__ __launch_bounds__(256) void prep_w_kernel(
    const float* __restrict__ w_qkv, const float* __restrict__ w_proj)
{
    int i = blockIdx.x * 256 + threadIdx.x;
    if (i < WQ_SZ) g_Wqh[i] = __float2half_rn(w_qkv[i]);
    else           g_Wph[i - WQ_SZ] = __float2half_rn(w_proj[i - WQ_SZ]);
}

// ---------------------------------------------------------------------------
// Prep 2: transpose + split x: [b][c][n] fp32 -> [b][n][c] fp16 hi/lo.
// ---------------------------------------------------------------------------
__global__ __launch_bounds__(256) void prep_x_kernel(const float* __restrict__ x)
{
    __shared__ float ts[32][132];
    const int b  = blockIdx.z;
    const int c0 = blockIdx.y * 32;
    const int n0 = blockIdx.x * 128;
    const int t  = threadIdx.x;

    {
        int cc = t >> 3, nseg = t & 7;
        const float* src = x + b * (C_ * N_) + (c0 + cc) * N_ + n0 + nseg * 16;
        #pragma unroll
        for (int j = 0; j < 4; j++) {
            float4 v = *(const float4*)(src + j * 4);
            int nn = nseg * 16 + j * 4;
            ts[cc][nn] = v.x; ts[cc][nn+1] = v.y; ts[cc][nn+2] = v.z; ts[cc][nn+3] = v.w;
        }
    }
    __syncthreads();
    {
        int nn = t & 127, arr = t >> 7;
        unsigned w[16];
        #pragma unroll
        for (int cc = 0; cc < 32; cc += 2) {
            float v0 = ts[cc][nn], v1 = ts[cc+1][nn];
            __half h0 = __float2half_rn(v0);
            __half h1 = __float2half_rn(v1);
            if (arr) {
                h0 = __float2half_rn(v0 - __half2float(h0));
                h1 = __float2half_rn(v1 - __half2float(h1));
            }
            w[cc >> 1] = pack_f16x2(h0, h1);
        }
        __half* dst = (arr ? g_Xl : g_Xh) + b * (N_ * C_) + (size_t)(n0 + nn) * C_ + c0;
        uint4* d4 = (uint4*)dst;
        #pragma unroll
        for (int j = 0; j < 4; j++)
            d4[j] = make_uint4(w[j*4], w[j*4+1], w[j*4+2], w[j*4+3]);
    }
}

// ---------------------------------------------------------------------------
// fp16 GEMM (2-term: Ah*Bh + Ah*Bl): CTA 128x64, BK=32, double-buffered
// cp.async, ldmatrix frags.
// MODE 0 (QKV): fp16 Q/K [bh][n][d], V [bh][d][n].
// MODE 1 (proj): + bias + residual -> g_Y fp32.
// ---------------------------------------------------------------------------
template <int MODE>
__global__ __launch_bounds__(256) void gemm_f16_kernel(
    const __half* __restrict__ Agh,
    const __half* __restrict__ Bgh, const __half* __restrict__ Bgl,
    const float* __restrict__ bias, const float* __restrict__ x)
{
    constexpr int S_AH = 0;
    constexpr int S_BH = 5120;
    constexpr int S_BL = 7680;
    constexpr int STAGE = 10240;

    extern __shared__ __half smh[];
    const unsigned smem_base = (unsigned)__cvta_generic_to_shared(smh);

    const int b  = blockIdx.z;
    const int o0 = blockIdx.y * 128;
    const int n0 = blockIdx.x * 64;
    const int tid  = threadIdx.x;
    const int warp = tid >> 5;
    const int lane = tid & 31;
    const int g = lane >> 2;
    const int q = lane & 3;
    const int wm = (warp >> 1) * 32;
    const int wn = (warp & 1) * 32;
    const int arow  = lane & 15;
    const int acol8 = (lane >> 4) * 8;
    const int brow  = lane & 7;
    const int bcol8 = (lane >> 3) * 8;

    const __half* bgh = Bgh + (size_t)b * (N_ * C_);
    const __half* bgl = Bgl + (size_t)b * (N_ * C_);

    float acc[2][4][4] = {};

    auto load_tile = [&](int kt, int s) {
        const int kk = kt * 32;
        const unsigned sb = smem_base + s * (STAGE * 2);
        #pragma unroll
        for (int i = 0; i < 2; i++) {
            int c = tid + i * 256;
            int m = c >> 2, ck = c & 3;
            const __half* src = Agh + (o0 + m) * C_ + kk + ck * 8;
            unsigned dst = sb + S_AH * 2 + (m * 40 + ck * 8) * 2;
            cp_async16(dst, src);
        }
        #pragma unroll
        for (int i = 0; i < 2; i++) {
            int idx = tid + i * 256;
            int arr = idx >> 8;
            int c   = idx & 255;
            int n = c >> 2, ck = c & 3;
            const __half* src = (arr ? bgl : bgh) + (size_t)(n0 + n) * C_ + kk + ck * 8;
            unsigned dst = sb + (arr ? S_BL : S_BH) * 2 + (n * 40 + ck * 8) * 2;
            cp_async16(dst, src);
        }
        asm volatile("cp.async.commit_group;" ::: "memory");
    };

    load_tile(0, 0);

    const int NKT = C_ / 32;
    for (int kt = 0; kt < NKT; kt++) {
        if (kt + 1 < NKT) {
            load_tile(kt + 1, (kt + 1) & 1);
            asm volatile("cp.async.wait_group 1;" ::: "memory");
        } else {
            asm volatile("cp.async.wait_group 0;" ::: "memory");
        }
        __syncthreads();

        const unsigned sb = smem_base + (kt & 1) * (STAGE * 2);

        unsigned bhf[4][4], blf[4][4];
        #pragma unroll
        for (int ni = 0; ni < 4; ni++) {
            unsigned off = ((wn + ni * 8 + brow) * 40 + bcol8) * 2;
            ldmatrix_x4(bhf[ni][0], bhf[ni][1], bhf[ni][2], bhf[ni][3],
                        sb + S_BH * 2 + off);
            ldmatrix_x4(blf[ni][0], blf[ni][1], blf[ni][2], blf[ni][3],
                        sb + S_BL * 2 + off);
        }

        #pragma unroll
        for (int kb = 0; kb < 2; kb++) {
            unsigned ah[2][4];
            #pragma unroll
            for (int mi = 0; mi < 2; mi++) {
                unsigned off = ((wm + mi * 16 + arow) * 40 + kb * 16 + acol8) * 2;
                ldmatrix_x4(ah[mi][0], ah[mi][1], ah[mi][2], ah[mi][3],
                            sb + S_AH * 2 + off);
            }
            #pragma unroll
            for (int ni = 0; ni < 4; ni++) {
                unsigned b0h = bhf[ni][2*kb], b1h = bhf[ni][2*kb+1];
                unsigned b0l = blf[ni][2*kb], b1l = blf[ni][2*kb+1];
                #pragma unroll
                for (int mi = 0; mi < 2; mi++) {
                    mma_f16(acc[mi][ni], ah[mi][0], ah[mi][1], ah[mi][2], ah[mi][3], b0h, b1h);
                    mma_f16(acc[mi][ni], ah[mi][0], ah[mi][1], ah[mi][2], ah[mi][3], b0l, b1l);
                }
            }
        }
        __syncthreads();
    }

    if (MODE == 0) {
        const int s = o0 >> 8;                      // 0=q, 1=k, 2=v
        const float scale = (s == 0)
            ? 0.17677669529663687f * 1.4426950408889634f : 1.0f;
        if (s == 2) {
            #pragma unroll
            for (int mi = 0; mi < 2; mi++) {
                int o = o0 + wm + mi * 16 + g;
                float bv0 = bias[o], bv1 = bias[o + 8];
                int cd0 = o & 255, cd1 = (o + 8) & 255;
                #pragma unroll
                for (int ni = 0; ni < 4; ni++) {
                    int col = n0 + wn + ni * 8 + 2 * q;
                    unsigned p0 = cvt_f16x2(acc[mi][ni][1] + bv0, acc[mi][ni][0] + bv0);
                    unsigned p1 = cvt_f16x2(acc[mi][ni][3] + bv1, acc[mi][ni][2] + bv1);
                    *(unsigned*)&g_Vb[(size_t)(b * 256 + cd0) * N_ + col] = p0;
                    *(unsigned*)&g_Vb[(size_t)(b * 256 + cd1) * N_ + col] = p1;
                }
            }
        } else {
            float* Ts = (float*)smh;
            #pragma unroll
            for (int mi = 0; mi < 2; mi++) {
                int r0 = wm + mi * 16 + g;
                int o  = o0 + r0;
                float bv0 = bias[o], bv1 = bias[o + 8];
                #pragma unroll
                for (int ni = 0; ni < 4; ni++) {
                    int cl = wn + ni * 8 + 2 * q;
                    Ts[cl * 133 + r0]           = (acc[mi][ni][0] + bv0) * scale;
                    Ts[(cl + 1) * 133 + r0]     = (acc[mi][ni][1] + bv0) * scale;
                    Ts[cl * 133 + r0 + 8]       = (acc[mi][ni][2] + bv1) * scale;
                    Ts[(cl + 1) * 133 + r0 + 8] = (acc[mi][ni][3] + bv1) * scale;
                }
            }
            __syncthreads();
            int nl = tid & 63, hh = tid >> 6;
            int h0 = (o0 & 255) >> 5;
            int bh = b * 8 + h0 + hh;
            unsigned w[16];
            const float* row = Ts + nl * 133 + hh * 32;
            #pragma unroll
            for (int dd = 0; dd < 32; dd += 2)
                w[dd >> 1] = cvt_f16x2(row[dd + 1], row[dd]);
            __half* dst = (s == 0 ? g_Qb : g_Kb) + ((size_t)bh * N_ + n0 + nl) * 32;
            uint4* d4 = (uint4*)dst;
            #pragma unroll
            for (int j = 0; j < 4; j++)
                d4[j] = make_uint4(w[j*4], w[j*4+1], w[j*4+2], w[j*4+3]);
        }
    } else {
        const float* xb = x + b * (C_ * N_);
        float* yb = g_Y + b * (C_ * N_);
        #pragma unroll
        for (int mi = 0; mi < 2; mi++) {
            int o = o0 + wm + mi * 16 + g;
            float bv0 = bias[o], bv1 = bias[o + 8];
            #pragma unroll
            for (int ni = 0; ni < 4; ni++) {
                int col = n0 + wn + ni * 8 + 2 * q;
                float2 x0 = *(const float2*)&xb[o * N_ + col];
                float2 x1 = *(const float2*)&xb[(o + 8) * N_ + col];
                float2 v0, v1;
                v0.x = acc[mi][ni][0] + bv0 + x0.x;
                v0.y = acc[mi][ni][1] + bv0 + x0.y;
                v1.x = acc[mi][ni][2] + bv1 + x1.x;
                v1.y = acc[mi][ni][3] + bv1 + x1.y;
                *(float2*)&yb[o * N_ + col] = v0;
                *(float2*)&yb[(o + 8) * N_ + col] = v1;
            }
        }
    }
}

// ---------------------------------------------------------------------------
// Flash attention, fp16. CTA = 128 queries of one (b,h), 4 warps x 32 rows
// (best measured config). QK on f16-accum mma; packed D-fragments feed
// ex2.approx.f16x2 directly; results are PV A-fragments. l via kj-pre-summed
// A-fragments (f16x2 adds on idle ALU pipe) + ONE ones-mma per mi (was 4).
// 3-stage cp.async pipeline, one barrier per tile. No running max.
// ---------------------------------------------------------------------------
#define AQ_H 5120                          // Qs[128][40]
#define STG_H 4864                         // 2560 (Ks[64][40]) + 2304 (Vt[32][72])
#define ATTN_SMEM_H (AQ_H + 3*STG_H)       // 19712 halves = 39424 B
#define ONES_F16X2 0x3C003C00u

__global__ __launch_bounds__(128) void attn_kernel()
{
    extern __shared__ __half smh[];
    const unsigned smem_base = (unsigned)__cvta_generic_to_shared(smh);

    const int bh   = blockIdx.y;
    const int n0   = blockIdx.x * 128;
    const int tid  = threadIdx.x;
    const int warp = tid >> 5;
    const int lane = tid & 31;
    const int g    = lane >> 2;
    const int q    = lane & 3;
    const int lrow = lane & 7;
    const int lcol8 = (lane >> 3) * 8;

    const __half* Qg = g_Qb + (size_t)bh * N_ * 32;
    const __half* Kg = g_Kb + (size_t)bh * N_ * 32;
    const __half* Vg = g_Vb + (size_t)bh * 32 * N_;

    auto load_kv = [&](int t, int s) {
        const unsigned sb = smem_base + (AQ_H + s * STG_H) * 2;
        #pragma unroll
        for (int i = 0; i < 2; i++) {
            int c = tid + i * 128;
            int j = c >> 2, off = (c & 3) * 8;
            cp_async16(sb + (j * 40 + off) * 2, Kg + (size_t)(t + j) * 32 + off);
        }
        #pragma unroll
        for (int i = 0; i < 2; i++) {
            int c = tid + i * 128;
            int dd = c >> 3, joff = (c & 7) * 8;
            cp_async16(sb + (2560 + dd * 72 + joff) * 2, Vg + (size_t)dd * N_ + t + joff);
        }
        asm volatile("cp.async.commit_group;" ::: "memory");
    };

    // Prologue: Q tile (128x32) + stages 0,1
    #pragma unroll
    for (int i = 0; i < 4; i++) {
        int c = tid + i * 128;
        int n = c >> 2, off = (c & 3) * 8;
        cp_async16(smem_base + (n * 40 + off) * 2, Qg + (size_t)(n0 + n) * 32 + off);
    }
    load_kv(0, 0);
    load_kv(64, 1);
    asm volatile("cp.async.wait_group 1;" ::: "memory");
    __syncthreads();

    unsigned qa[2][2][4];
    {
        int arow = lane & 15, acol8q = (lane >> 4) * 8;
        #pragma unroll
        for (int mi = 0; mi < 2; mi++) {
            #pragma unroll
            for (int kb = 0; kb < 2; kb++) {
                unsigned off = ((warp * 32 + mi * 16 + arow) * 40 + kb * 16 + acol8q) * 2;
                ldmatrix_x4(qa[mi][kb][0], qa[mi][kb][1], qa[mi][kb][2], qa[mi][kb][3],
                            smem_base + off);
            }
        }
    }

    float o[2][4][4] = {};
    float lac[2][4] = {};

    const int NT = N_ / 64;  // 32
    int st = 0, ldst = 2;
    for (int t = 0; t < NT; t++) {
        if (t + 1 < NT) {
            asm volatile("cp.async.wait_group 1;" ::: "memory");
        } else {
            asm volatile("cp.async.wait_group 0;" ::: "memory");
        }
        __syncthreads();
        if (t + 2 < NT) load_kv((t + 2) * 64, ldst);

        const unsigned ks_u32 = smem_base + (AQ_H + st * STG_H) * 2;
        const unsigned vt_u32 = ks_u32 + 2560 * 2;

        // S = Q K^T on f16-accum mma
        unsigned su[2][8][2] = {};
        #pragma unroll
        for (int ni = 0; ni < 8; ni++) {
            unsigned kf0, kf1, kf2, kf3;
            ldmatrix_x4(kf0, kf1, kf2, kf3,
                        ks_u32 + ((ni * 8 + lrow) * 40 + lcol8) * 2);
            #pragma unroll
            for (int mi = 0; mi < 2; mi++) {
                mma_f16acc(su[mi][ni][0], su[mi][ni][1],
                           qa[mi][0][0], qa[mi][0][1], qa[mi][0][2], qa[mi][0][3],
                           kf0, kf1);
                mma_f16acc(su[mi][ni][0], su[mi][ni][1],
                           qa[mi][1][0], qa[mi][1][1], qa[mi][1][2], qa[mi][1][3],
                           kf2, kf3);
            }
        }

        // p = 2^s
        unsigned pu[2][8][2];
        #pragma unroll
        for (int mi = 0; mi < 2; mi++) {
            #pragma unroll
            for (int ni = 0; ni < 8; ni++) {
                pu[mi][ni][0] = ex2_f16x2(su[mi][ni][0]);
                pu[mi][ni][1] = ex2_f16x2(su[mi][ni][1]);
            }
        }

        // O += P V
        #pragma unroll
        for (int ni = 0; ni < 4; ni++) {
            unsigned vf[8];
            unsigned va = vt_u32 + ((ni * 8 + lrow) * 72 + lcol8) * 2;
            ldmatrix_x4(vf[0], vf[1], vf[2], vf[3], va);
            ldmatrix_x4(vf[4], vf[5], vf[6], vf[7], va + 64);
            #pragma unroll
            for (int kj = 0; kj < 4; kj++) {
                #pragma unroll
                for (int mi = 0; mi < 2; mi++) {
                    mma_f16(o[mi][ni],
                            pu[mi][2*kj][0], pu[mi][2*kj][1],
                            pu[mi][2*kj+1][0], pu[mi][2*kj+1][1],
                            vf[2*kj], vf[2*kj+1]);
                }
            }
        }
        // l += P * ones: pre-sum A-fragments over kj (f16x2 adds, ALU pipe),
        // then ONE ones-mma per mi. Safe: 4 * p_max = 2^15 < f16 max.
        #pragma unroll
        for (int mi = 0; mi < 2; mi++) {
            unsigned s0 = hadd2(hadd2(pu[mi][0][0], pu[mi][2][0]),
                                hadd2(pu[mi][4][0], pu[mi][6][0]));
            unsigned s1 = hadd2(hadd2(pu[mi][0][1], pu[mi][2][1]),
                                hadd2(pu[mi][4][1], pu[mi][6][1]));
            unsigned s2 = hadd2(hadd2(pu[mi][1][0], pu[mi][3][0]),
                                hadd2(pu[mi][5][0], pu[mi][7][0]));
            unsigned s3 = hadd2(hadd2(pu[mi][1][1], pu[mi][3][1]),
                                hadd2(pu[mi][5][1], pu[mi][7][1]));
            mma_f16(lac[mi], s0, s1, s2, s3, ONES_F16X2, ONES_F16X2);
        }

        if (++st == 3) st = 0;
        if (++ldst == 3) ldst = 0;
    }

    float linv[4];
    linv[0] = 1.f / lac[0][0];
    linv[1] = 1.f / lac[0][2];
    linv[2] = 1.f / lac[1][0];
    linv[3] = 1.f / lac[1][2];

    __syncthreads();
    float* Os = (float*)smh;  // [128][33]
    #pragma unroll
    for (int mi = 0; mi < 2; mi++) {
        int r = warp * 32 + mi * 16 + g;
        #pragma unroll
        for (int ni = 0; ni < 4; ni++) {
            int dcol = ni * 8 + 2 * q;
            Os[r * 33 + dcol]           = o[mi][ni][0] * linv[mi * 2];
            Os[r * 33 + dcol + 1]       = o[mi][ni][1] * linv[mi * 2];
            Os[(r + 8) * 33 + dcol]     = o[mi][ni][2] * linv[mi * 2 + 1];
            Os[(r + 8) * 33 + dcol + 1] = o[mi][ni][3] * linv[mi * 2 + 1];
        }
    }
    __syncthreads();
    {
        int b = bh >> 3, h = bh & 7;
        unsigned hw[16], lw[16];
        #pragma unroll
        for (int dd = 0; dd < 32; dd += 2) {
            float v0 = Os[tid * 33 + dd];
            float v1 = Os[tid * 33 + dd + 1];
            __half h0 = __float2half_rn(v0);
            __half h1 = __float2half_rn(v1);
            __half l0 = __float2half_rn(v0 - __half2float(h0));
            __half l1 = __float2half_rn(v1 - __half2float(h1));
            hw[dd >> 1] = pack_f16x2(h0, h1);
            lw[dd >> 1] = pack_f16x2(l0, l1);
        }
        size_t base = (size_t)b * (N_ * C_) + (size_t)(n0 + tid) * C_ + h * 32;
        uint4* dh = (uint4*)(g_AOh + base);
        uint4* dl = (uint4*)(g_AOl + base);
        #pragma unroll
        for (int j = 0; j < 4; j++) {
            dh[j] = make_uint4(hw[j*4], hw[j*4+1], hw[j*4+2], hw[j*4+3]);
            dl[j] = make_uint4(lw[j*4], lw[j*4+1], lw[j*4+2], lw[j*4+3]);
        }
    }
}

// ---------------------------------------------------------------------------
// LayerNorm over channels. Block: 32 n-cols x 8 c-groups. Grid (N/32, B).
// ---------------------------------------------------------------------------
__global__ __launch_bounds__(256) void ln_kernel(
    const float* __restrict__ ln_g, const float* __restrict__ ln_b,
    float* __restrict__ out)
{
    __shared__ float ssum[8][32], ssq[8][32];
    __shared__ float smu[32], srstd[32];

    const int batch = blockIdx.y;
    const int nc = threadIdx.x & 31;
    const int cg = threadIdx.x >> 5;
    const int n  = blockIdx.x * 32 + nc;
    const float* Yb = g_Y + batch * (C_ * N_) + n;

    float sum = 0.f, sq = 0.f;
    #pragma unroll 8
    for (int i = 0; i < 32; i++) {
        float v = Yb[(cg * 32 + i) * N_];
        sum += v; sq += v * v;
    }
    ssum[cg][nc] = sum; ssq[cg][nc] = sq;
    __syncthreads();
    if (cg == 0) {
        float s = 0.f, qq = 0.f;
        #pragma unroll
        for (int j = 0; j < 8; j++) { s += ssum[j][nc]; qq += ssq[j][nc]; }
        float mu = s * (1.f / C_);
        float var = qq * (1.f / C_) - mu * mu;
        smu[nc] = mu; srstd[nc] = rsqrtf(var + 1e-5f);
    }
    __syncthreads();
    float mu = smu[nc], rs = srstd[nc];
    float* ob = out + batch * (C_ * N_) + n;
    #pragma unroll 8
    for (int i = 0; i < 32; i++) {
        int c = cg * 32 + i;
        float v = Yb[c * N_];
        ob[c * N_] = (v - mu) * rs * ln_g[c] + ln_b[c];
    }
}

// ---------------------------------------------------------------------------
extern "C" void kernel_launch(void* const* d_in, const int* in_sizes, int n_in,
                              void* d_out, int out_size)
{
    const float* x      = (const float*)d_in[0];
    const float* w_qkv  = (const float*)d_in[1];
    const float* b_qkv  = (const float*)d_in[2];
    const float* w_proj = (const float*)d_in[3];
    const float* b_proj = (const float*)d_in[4];
    const float* ln_g   = (const float*)d_in[5];
    const float* ln_b   = (const float*)d_in[6];
    float* out = (float*)d_out;

    const int gemm_smem = 2 * 10240 * 2;    // 40960 B
    const int attn_smem = ATTN_SMEM_H * 2;  // 39424 B
    cudaFuncSetAttribute(gemm_f16_kernel<0>,
                         cudaFuncAttributeMaxDynamicSharedMemorySize, gemm_smem);
    cudaFuncSetAttribute(gemm_f16_kernel<1>,
                         cudaFuncAttributeMaxDynamicSharedMemorySize, gemm_smem);
    cudaFuncSetAttribute(attn_kernel,
                         cudaFuncAttributeMaxDynamicSharedMemorySize, attn_smem);

    __half *p_Wqh, *p_Wph, *p_Xh, *p_Xl, *p_AOh, *p_AOl;
    cudaGetSymbolAddress((void**)&p_Wqh, g_Wqh);
    cudaGetSymbolAddress((void**)&p_Wph, g_Wph);
    cudaGetSymbolAddress((void**)&p_Xh,  g_Xh);
    cudaGetSymbolAddress((void**)&p_Xl,  g_Xl);
    cudaGetSymbolAddress((void**)&p_AOh, g_AOh);
    cudaGetSymbolAddress((void**)&p_AOl, g_AOl);

    prep_w_kernel<<<(WQ_SZ + WP_SZ) / 256, 256>>>(w_qkv, w_proj);
    prep_x_kernel<<<dim3(N_ / 128, C_ / 32, B_), 256>>>(x);
    gemm_f16_kernel<0><<<dim3(N_ / 64, (3 * C_) / 128, B_), 256, gemm_smem>>>(
        p_Wqh, p_Xh, p_Xl, b_qkv, nullptr);
    attn_kernel<<<dim3(N_ / 128, B_ * H_), 128, attn_smem>>>();
    gemm_f16_kernel<1><<<dim3(N_ / 64, C_ / 128, B_), 256, gemm_smem>>>(
        p_Wph, p_AOh, p_AOl, b_proj, x);
    ln_kernel<<<dim3(N_ / 32, B_), 256>>>(ln_g, ln_b, out);
}

// round 15
// speedup vs baseline: 1.1197x; 1.0038x over previous
#include <cuda_runtime.h>
#include <cuda_fp16.h>

#define B_ 4
#define C_ 256
#define N_ 2048
#define H_ 8
#define D_ 32

// Scratch (allocation-free rule: __device__ globals)
__device__ __half g_Qb[B_*C_*N_];    // [bh][n][d] fp16, pre-scaled by D^-0.5*log2e
__device__ __half g_Kb[B_*C_*N_];    // [bh][n][d] fp16
__device__ __half g_Vb[B_*C_*N_];    // [bh][d][n] fp16
__device__ __half g_Xh[B_*N_*C_];    // x transposed [b][n][c] fp16 hi/lo
__device__ __half g_Xl[B_*N_*C_];
__device__ __half g_AOh[B_*N_*C_];   // attention out [b][n][c] fp16 hi/lo
__device__ __half g_AOl[B_*N_*C_];
__device__ __half g_Wqh[3*C_*C_];    // QKV weights: fp16 hi only (2-term GEMM)
__device__ __half g_Wph[C_*C_];      // proj weights: fp16 hi only (2-term GEMM)

// fp16 inputs, fp32 accumulator
__device__ __forceinline__ void mma_f16(float* d, unsigned a0, unsigned a1,
                                        unsigned a2, unsigned a3,
                                        unsigned b0, unsigned b1) {
    asm volatile(
        "mma.sync.aligned.m16n8k16.row.col.f32.f16.f16.f32 "
        "{%0,%1,%2,%3}, {%4,%5,%6,%7}, {%8,%9}, {%0,%1,%2,%3};\n"
        : "+f"(d[0]), "+f"(d[1]), "+f"(d[2]), "+f"(d[3])
        : "r"(a0), "r"(a1), "r"(a2), "r"(a3), "r"(b0), "r"(b1));
}

// fp16 inputs, fp16 accumulator; D packed {c0,c1},{c2,c3}
__device__ __forceinline__ void mma_f16acc(unsigned& d0, unsigned& d1,
                                           unsigned a0, unsigned a1,
                                           unsigned a2, unsigned a3,
                                           unsigned b0, unsigned b1) {
    asm volatile(
        "mma.sync.aligned.m16n8k16.row.col.f16.f16.f16.f16 "
        "{%0,%1}, {%2,%3,%4,%5}, {%6,%7}, {%0,%1};\n"
        : "+r"(d0), "+r"(d1)
        : "r"(a0), "r"(a1), "r"(a2), "r"(a3), "r"(b0), "r"(b1));
}

__device__ __forceinline__ void ldmatrix_x4(unsigned& r0, unsigned& r1,
                                            unsigned& r2, unsigned& r3,
                                            unsigned addr) {
    asm volatile("ldmatrix.sync.aligned.m8n8.x4.shared.b16 {%0,%1,%2,%3}, [%4];"
                 : "=r"(r0), "=r"(r1), "=r"(r2), "=r"(r3) : "r"(addr));
}

__device__ __forceinline__ void cp_async16(unsigned dst, const void* src) {
    asm volatile("cp.async.cg.shared.global [%0], [%1], 16;"
                 :: "r"(dst), "l"(src));
}
__device__ __forceinline__ unsigned pack_f16x2(__half a, __half b) {
    unsigned short ua = *(unsigned short*)&a;
    unsigned short ub = *(unsigned short*)&b;
    return (unsigned)ua | ((unsigned)ub << 16);
}
// packs {lo, hi} into f16x2 (lo -> lower 16 bits)
__device__ __forceinline__ unsigned cvt_f16x2(float hi, float lo) {
    unsigned r;
    asm("cvt.rn.f16x2.f32 %0, %1, %2;" : "=r"(r) : "f"(hi), "f"(lo));
    return r;
}
// elementwise 2^x on an f16x2 pair
__device__ __forceinline__ unsigned ex2_f16x2(unsigned x) {
    unsigned r;
    asm("ex2.approx.f16x2 %0, %1;" : "=r"(r) : "r"(x));
    return r;
}
// elementwise f16x2 add
__device__ __forceinline__ unsigned hadd2(unsigned a, unsigned b) {
    unsigned r;
    asm("add.rn.f16x2 %0, %1, %2;" : "=r"(r) : "r"(a), "r"(b));
    return r;
}

// ---------------------------------------------------------------------------
// Prep 1: weights -> fp16 hi only (both GEMMs are 2-term).
// ---------------------------------------------------------------------------
#define WQ_SZ (3*C_*C_)
#define WP_SZ (C_*C_)
__global__ __launch_bounds__(256) void prep_w_kernel(
    const float* __restrict__ w_qkv, const float* __restrict__ w_proj)
{
    int i = blockIdx.x * 256 + threadIdx.x;
    if (i < WQ_SZ) g_Wqh[i] = __float2half_rn(w_qkv[i]);
    else           g_Wph[i - WQ_SZ] = __float2half_rn(w_proj[i - WQ_SZ]);
}

// ---------------------------------------------------------------------------
// Prep 2: transpose + split x: [b][c][n] fp32 -> [b][n][c] fp16 hi/lo.
// ---------------------------------------------------------------------------
__global__ __launch_bounds__(256) void prep_x_kernel(const float* __restrict__ x)
{
    __shared__ float ts[32][132];
    const int b  = blockIdx.z;
    const int c0 = blockIdx.y * 32;
    const int n0 = blockIdx.x * 128;
    const int t  = threadIdx.x;

    {
        int cc = t >> 3, nseg = t & 7;
        const float* src = x + b * (C_ * N_) + (c0 + cc) * N_ + n0 + nseg * 16;
        #pragma unroll
        for (int j = 0; j < 4; j++) {
            float4 v = *(const float4*)(src + j * 4);
            int nn = nseg * 16 + j * 4;
            ts[cc][nn] = v.x; ts[cc][nn+1] = v.y; ts[cc][nn+2] = v.z; ts[cc][nn+3] = v.w;
        }
    }
    __syncthreads();
    {
        int nn = t & 127, arr = t >> 7;
        unsigned w[16];
        #pragma unroll
        for (int cc = 0; cc < 32; cc += 2) {
            float v0 = ts[cc][nn], v1 = ts[cc+1][nn];
            __half h0 = __float2half_rn(v0);
            __half h1 = __float2half_rn(v1);
            if (arr) {
                h0 = __float2half_rn(v0 - __half2float(h0));
                h1 = __float2half_rn(v1 - __half2float(h1));
            }
            w[cc >> 1] = pack_f16x2(h0, h1);
        }
        __half* dst = (arr ? g_Xl : g_Xh) + b * (N_ * C_) + (size_t)(n0 + nn) * C_ + c0;
        uint4* d4 = (uint4*)dst;
        #pragma unroll
        for (int j = 0; j < 4; j++)
            d4[j] = make_uint4(w[j*4], w[j*4+1], w[j*4+2], w[j*4+3]);
    }
}

// ---------------------------------------------------------------------------
// QKV GEMM (2-term: Ah*Bh + Ah*Bl): CTA 128x64, BK=32, double-buffered
// cp.async, ldmatrix frags. fp16 Q/K [bh][n][d], V [bh][d][n].
// ---------------------------------------------------------------------------
__global__ __launch_bounds__(256) void qkv_gemm_kernel(
    const __half* __restrict__ Agh,
    const __half* __restrict__ Bgh, const __half* __restrict__ Bgl,
    const float* __restrict__ bias)
{
    constexpr int S_AH = 0;
    constexpr int S_BH = 5120;
    constexpr int S_BL = 7680;
    constexpr int STAGE = 10240;

    extern __shared__ __half smh[];
    const unsigned smem_base = (unsigned)__cvta_generic_to_shared(smh);

    const int b  = blockIdx.z;
    const int o0 = blockIdx.y * 128;
    const int n0 = blockIdx.x * 64;
    const int tid  = threadIdx.x;
    const int warp = tid >> 5;
    const int lane = tid & 31;
    const int g = lane >> 2;
    const int q = lane & 3;
    const int wm = (warp >> 1) * 32;
    const int wn = (warp & 1) * 32;
    const int arow  = lane & 15;
    const int acol8 = (lane >> 4) * 8;
    const int brow  = lane & 7;
    const int bcol8 = (lane >> 3) * 8;

    const __half* bgh = Bgh + (size_t)b * (N_ * C_);
    const __half* bgl = Bgl + (size_t)b * (N_ * C_);

    float acc[2][4][4] = {};

    auto load_tile = [&](int kt, int s) {
        const int kk = kt * 32;
        const unsigned sb = smem_base + s * (STAGE * 2);
        #pragma unroll
        for (int i = 0; i < 2; i++) {
            int c = tid + i * 256;
            int m = c >> 2, ck = c & 3;
            const __half* src = Agh + (o0 + m) * C_ + kk + ck * 8;
            unsigned dst = sb + S_AH * 2 + (m * 40 + ck * 8) * 2;
            cp_async16(dst, src);
        }
        #pragma unroll
        for (int i = 0; i < 2; i++) {
            int idx = tid + i * 256;
            int arr = idx >> 8;
            int c   = idx & 255;
            int n = c >> 2, ck = c & 3;
            const __half* src = (arr ? bgl : bgh) + (size_t)(n0 + n) * C_ + kk + ck * 8;
            unsigned dst = sb + (arr ? S_BL : S_BH) * 2 + (n * 40 + ck * 8) * 2;
            cp_async16(dst, src);
        }
        asm volatile("cp.async.commit_group;" ::: "memory");
    };

    load_tile(0, 0);

    const int NKT = C_ / 32;
    for (int kt = 0; kt < NKT; kt++) {
        if (kt + 1 < NKT) {
            load_tile(kt + 1, (kt + 1) & 1);
            asm volatile("cp.async.wait_group 1;" ::: "memory");
        } else {
            asm volatile("cp.async.wait_group 0;" ::: "memory");
        }
        __syncthreads();

        const unsigned sb = smem_base + (kt & 1) * (STAGE * 2);

        unsigned bhf[4][4], blf[4][4];
        #pragma unroll
        for (int ni = 0; ni < 4; ni++) {
            unsigned off = ((wn + ni * 8 + brow) * 40 + bcol8) * 2;
            ldmatrix_x4(bhf[ni][0], bhf[ni][1], bhf[ni][2], bhf[ni][3],
                        sb + S_BH * 2 + off);
            ldmatrix_x4(blf[ni][0], blf[ni][1], blf[ni][2], blf[ni][3],
                        sb + S_BL * 2 + off);
        }

        #pragma unroll
        for (int kb = 0; kb < 2; kb++) {
            unsigned ah[2][4];
            #pragma unroll
            for (int mi = 0; mi < 2; mi++) {
                unsigned off = ((wm + mi * 16 + arow) * 40 + kb * 16 + acol8) * 2;
                ldmatrix_x4(ah[mi][0], ah[mi][1], ah[mi][2], ah[mi][3],
                            sb + S_AH * 2 + off);
            }
            #pragma unroll
            for (int ni = 0; ni < 4; ni++) {
                unsigned b0h = bhf[ni][2*kb], b1h = bhf[ni][2*kb+1];
                unsigned b0l = blf[ni][2*kb], b1l = blf[ni][2*kb+1];
                #pragma unroll
                for (int mi = 0; mi < 2; mi++) {
                    mma_f16(acc[mi][ni], ah[mi][0], ah[mi][1], ah[mi][2], ah[mi][3], b0h, b1h);
                    mma_f16(acc[mi][ni], ah[mi][0], ah[mi][1], ah[mi][2], ah[mi][3], b0l, b1l);
                }
            }
        }
        __syncthreads();
    }

    const int s = o0 >> 8;                      // 0=q, 1=k, 2=v
    const float scale = (s == 0)
        ? 0.17677669529663687f * 1.4426950408889634f : 1.0f;
    if (s == 2) {
        #pragma unroll
        for (int mi = 0; mi < 2; mi++) {
            int o = o0 + wm + mi * 16 + g;
            float bv0 = bias[o], bv1 = bias[o + 8];
            int cd0 = o & 255, cd1 = (o + 8) & 255;
            #pragma unroll
            for (int ni = 0; ni < 4; ni++) {
                int col = n0 + wn + ni * 8 + 2 * q;
                unsigned p0 = cvt_f16x2(acc[mi][ni][1] + bv0, acc[mi][ni][0] + bv0);
                unsigned p1 = cvt_f16x2(acc[mi][ni][3] + bv1, acc[mi][ni][2] + bv1);
                *(unsigned*)&g_Vb[(size_t)(b * 256 + cd0) * N_ + col] = p0;
                *(unsigned*)&g_Vb[(size_t)(b * 256 + cd1) * N_ + col] = p1;
            }
        }
    } else {
        float* Ts = (float*)smh;
        #pragma unroll
        for (int mi = 0; mi < 2; mi++) {
            int r0 = wm + mi * 16 + g;
            int o  = o0 + r0;
            float bv0 = bias[o], bv1 = bias[o + 8];
            #pragma unroll
            for (int ni = 0; ni < 4; ni++) {
                int cl = wn + ni * 8 + 2 * q;
                Ts[cl * 133 + r0]           = (acc[mi][ni][0] + bv0) * scale;
                Ts[(cl + 1) * 133 + r0]     = (acc[mi][ni][1] + bv0) * scale;
                Ts[cl * 133 + r0 + 8]       = (acc[mi][ni][2] + bv1) * scale;
                Ts[(cl + 1) * 133 + r0 + 8] = (acc[mi][ni][3] + bv1) * scale;
            }
        }
        __syncthreads();
        int nl = tid & 63, hh = tid >> 6;
        int h0 = (o0 & 255) >> 5;
        int bh = b * 8 + h0 + hh;
        unsigned w[16];
        const float* row = Ts + nl * 133 + hh * 32;
        #pragma unroll
        for (int dd = 0; dd < 32; dd += 2)
            w[dd >> 1] = cvt_f16x2(row[dd + 1], row[dd]);
        __half* dst = (s == 0 ? g_Qb : g_Kb) + ((size_t)bh * N_ + n0 + nl) * 32;
        uint4* d4 = (uint4*)dst;
        #pragma unroll
        for (int j = 0; j < 4; j++)
            d4[j] = make_uint4(w[j*4], w[j*4+1], w[j*4+2], w[j*4+3]);
    }
}

// ---------------------------------------------------------------------------
// Flash attention, fp16. CTA = 128 queries of one (b,h), 4 warps x 32 rows.
// QK on f16-accum mma; D-fragments feed ex2.approx.f16x2 directly; results
// are PV A-fragments. l via kj-pre-summed fragments + one ones-mma per mi.
// 3-stage cp.async pipeline, one barrier per tile. No running max.
// ---------------------------------------------------------------------------
#define AQ_H 5120                          // Qs[128][40]
#define STG_H 4864                         // 2560 (Ks[64][40]) + 2304 (Vt[32][72])
#define ATTN_SMEM_H (AQ_H + 3*STG_H)       // 19712 halves = 39424 B
#define ONES_F16X2 0x3C003C00u

__global__ __launch_bounds__(128) void attn_kernel()
{
    extern __shared__ __half smh[];
    const unsigned smem_base = (unsigned)__cvta_generic_to_shared(smh);

    const int bh   = blockIdx.y;
    const int n0   = blockIdx.x * 128;
    const int tid  = threadIdx.x;
    const int warp = tid >> 5;
    const int lane = tid & 31;
    const int g    = lane >> 2;
    const int q    = lane & 3;
    const int lrow = lane & 7;
    const int lcol8 = (lane >> 3) * 8;

    const __half* Qg = g_Qb + (size_t)bh * N_ * 32;
    const __half* Kg = g_Kb + (size_t)bh * N_ * 32;
    const __half* Vg = g_Vb + (size_t)bh * 32 * N_;

    auto load_kv = [&](int t, int s) {
        const unsigned sb = smem_base + (AQ_H + s * STG_H) * 2;
        #pragma unroll
        for (int i = 0; i < 2; i++) {
            int c = tid + i * 128;
            int j = c >> 2, off = (c & 3) * 8;
            cp_async16(sb + (j * 40 + off) * 2, Kg + (size_t)(t + j) * 32 + off);
        }
        #pragma unroll
        for (int i = 0; i < 2; i++) {
            int c = tid + i * 128;
            int dd = c >> 3, joff = (c & 7) * 8;
            cp_async16(sb + (2560 + dd * 72 + joff) * 2, Vg + (size_t)dd * N_ + t + joff);
        }
        asm volatile("cp.async.commit_group;" ::: "memory");
    };

    #pragma unroll
    for (int i = 0; i < 4; i++) {
        int c = tid + i * 128;
        int n = c >> 2, off = (c & 3) * 8;
        cp_async16(smem_base + (n * 40 + off) * 2, Qg + (size_t)(n0 + n) * 32 + off);
    }
    load_kv(0, 0);
    load_kv(64, 1);
    asm volatile("cp.async.wait_group 1;" ::: "memory");
    __syncthreads();

    unsigned qa[2][2][4];
    {
        int arow = lane & 15, acol8q = (lane >> 4) * 8;
        #pragma unroll
        for (int mi = 0; mi < 2; mi++) {
            #pragma unroll
            for (int kb = 0; kb < 2; kb++) {
                unsigned off = ((warp * 32 + mi * 16 + arow) * 40 + kb * 16 + acol8q) * 2;
                ldmatrix_x4(qa[mi][kb][0], qa[mi][kb][1], qa[mi][kb][2], qa[mi][kb][3],
                            smem_base + off);
            }
        }
    }

    float o[2][4][4] = {};
    float lac[2][4] = {};

    const int NT = N_ / 64;  // 32
    int st = 0, ldst = 2;
    for (int t = 0; t < NT; t++) {
        if (t + 1 < NT) {
            asm volatile("cp.async.wait_group 1;" ::: "memory");
        } else {
            asm volatile("cp.async.wait_group 0;" ::: "memory");
        }
        __syncthreads();
        if (t + 2 < NT) load_kv((t + 2) * 64, ldst);

        const unsigned ks_u32 = smem_base + (AQ_H + st * STG_H) * 2;
        const unsigned vt_u32 = ks_u32 + 2560 * 2;

        unsigned su[2][8][2] = {};
        #pragma unroll
        for (int ni = 0; ni < 8; ni++) {
            unsigned kf0, kf1, kf2, kf3;
            ldmatrix_x4(kf0, kf1, kf2, kf3,
                        ks_u32 + ((ni * 8 + lrow) * 40 + lcol8) * 2);
            #pragma unroll
            for (int mi = 0; mi < 2; mi++) {
                mma_f16acc(su[mi][ni][0], su[mi][ni][1],
                           qa[mi][0][0], qa[mi][0][1], qa[mi][0][2], qa[mi][0][3],
                           kf0, kf1);
                mma_f16acc(su[mi][ni][0], su[mi][ni][1],
                           qa[mi][1][0], qa[mi][1][1], qa[mi][1][2], qa[mi][1][3],
                           kf2, kf3);
            }
        }

        unsigned pu[2][8][2];
        #pragma unroll
        for (int mi = 0; mi < 2; mi++) {
            #pragma unroll
            for (int ni = 0; ni < 8; ni++) {
                pu[mi][ni][0] = ex2_f16x2(su[mi][ni][0]);
                pu[mi][ni][1] = ex2_f16x2(su[mi][ni][1]);
            }
        }

        #pragma unroll
        for (int ni = 0; ni < 4; ni++) {
            unsigned vf[8];
            unsigned va = vt_u32 + ((ni * 8 + lrow) * 72 + lcol8) * 2;
            ldmatrix_x4(vf[0], vf[1], vf[2], vf[3], va);
            ldmatrix_x4(vf[4], vf[5], vf[6], vf[7], va + 64);
            #pragma unroll
            for (int kj = 0; kj < 4; kj++) {
                #pragma unroll
                for (int mi = 0; mi < 2; mi++) {
                    mma_f16(o[mi][ni],
                            pu[mi][2*kj][0], pu[mi][2*kj][1],
                            pu[mi][2*kj+1][0], pu[mi][2*kj+1][1],
                            vf[2*kj], vf[2*kj+1]);
                }
            }
        }
        #pragma unroll
        for (int mi = 0; mi < 2; mi++) {
            unsigned s0 = hadd2(hadd2(pu[mi][0][0], pu[mi][2][0]),
                                hadd2(pu[mi][4][0], pu[mi][6][0]));
            unsigned s1 = hadd2(hadd2(pu[mi][0][1], pu[mi][2][1]),
                                hadd2(pu[mi][4][1], pu[mi][6][1]));
            unsigned s2 = hadd2(hadd2(pu[mi][1][0], pu[mi][3][0]),
                                hadd2(pu[mi][5][0], pu[mi][7][0]));
            unsigned s3 = hadd2(hadd2(pu[mi][1][1], pu[mi][3][1]),
                                hadd2(pu[mi][5][1], pu[mi][7][1]));
            mma_f16(lac[mi], s0, s1, s2, s3, ONES_F16X2, ONES_F16X2);
        }

        if (++st == 3) st = 0;
        if (++ldst == 3) ldst = 0;
    }

    float linv[4];
    linv[0] = 1.f / lac[0][0];
    linv[1] = 1.f / lac[0][2];
    linv[2] = 1.f / lac[1][0];
    linv[3] = 1.f / lac[1][2];

    __syncthreads();
    float* Os = (float*)smh;  // [128][33]
    #pragma unroll
    for (int mi = 0; mi < 2; mi++) {
        int r = warp * 32 + mi * 16 + g;
        #pragma unroll
        for (int ni = 0; ni < 4; ni++) {
            int dcol = ni * 8 + 2 * q;
            Os[r * 33 + dcol]           = o[mi][ni][0] * linv[mi * 2];
            Os[r * 33 + dcol + 1]       = o[mi][ni][1] * linv[mi * 2];
            Os[(r + 8) * 33 + dcol]     = o[mi][ni][2] * linv[mi * 2 + 1];
            Os[(r + 8) * 33 + dcol + 1] = o[mi][ni][3] * linv[mi * 2 + 1];
        }
    }
    __syncthreads();
    {
        int b = bh >> 3, h = bh & 7;
        unsigned hw[16], lw[16];
        #pragma unroll
        for (int dd = 0; dd < 32; dd += 2) {
            float v0 = Os[tid * 33 + dd];
            float v1 = Os[tid * 33 + dd + 1];
            __half h0 = __float2half_rn(v0);
            __half h1 = __float2half_rn(v1);
            __half l0 = __float2half_rn(v0 - __half2float(h0));
            __half l1 = __float2half_rn(v1 - __half2float(h1));
            hw[dd >> 1] = pack_f16x2(h0, h1);
            lw[dd >> 1] = pack_f16x2(l0, l1);
        }
        size_t base = (size_t)b * (N_ * C_) + (size_t)(n0 + tid) * C_ + h * 32;
        uint4* dh = (uint4*)(g_AOh + base);
        uint4* dl = (uint4*)(g_AOl + base);
        #pragma unroll
        for (int j = 0; j < 4; j++) {
            dh[j] = make_uint4(hw[j*4], hw[j*4+1], hw[j*4+2], hw[j*4+3]);
            dl[j] = make_uint4(lw[j*4], lw[j*4+1], lw[j*4+2], lw[j*4+3]);
        }
    }
}

// ---------------------------------------------------------------------------
// Fused proj GEMM + bias + residual + LayerNorm -> out.
// CTA: M=256 (ALL channels), N=32 n-cols, K=256, BK=32, 256 threads (8 warps
// x 32 channels). Y staged in smem fp32 [256][33]; in-CTA channel LN; writes
// final output. No g_Y round-trip, no separate LN kernel.
// ---------------------------------------------------------------------------
#define PL_A 0
#define PL_BH 10240
#define PL_BL 11520
#define PL_STAGE 12800                       // halves
#define PL_SMEM_BYTES (2 * PL_STAGE * 2)     // 51200 B
#define PL_RED_F 8704                        // float offset for reduce scratch

__global__ __launch_bounds__(256) void proj_ln_kernel(
    const __half* __restrict__ Wph,
    const __half* __restrict__ AOh, const __half* __restrict__ AOl,
    const float* __restrict__ bias, const float* __restrict__ x,
    const float* __restrict__ ln_g, const float* __restrict__ ln_b,
    float* __restrict__ out)
{
    extern __shared__ __half smh[];
    const unsigned smem_base = (unsigned)__cvta_generic_to_shared(smh);

    const int b  = blockIdx.y;
    const int n0 = blockIdx.x * 32;
    const int tid  = threadIdx.x;
    const int warp = tid >> 5;
    const int lane = tid & 31;
    const int g = lane >> 2;
    const int q = lane & 3;
    const int wm = warp * 32;            // channel base for this warp
    const int arow  = lane & 15;
    const int acol8 = (lane >> 4) * 8;
    const int brow  = lane & 7;
    const int bcol8 = (lane >> 3) * 8;

    const __half* bgh = AOh + (size_t)b * (N_ * C_);
    const __half* bgl = AOl + (size_t)b * (N_ * C_);

    float acc[2][4][4] = {};

    auto load_tile = [&](int kt, int s) {
        const int kk = kt * 32;
        const unsigned sb = smem_base + s * (PL_STAGE * 2);
        // A: 256 x 32 halves = 1024 chunks
        #pragma unroll
        for (int i = 0; i < 4; i++) {
            int c = tid + i * 256;
            int m = c >> 2, ck = c & 3;
            cp_async16(sb + PL_A * 2 + (m * 40 + ck * 8) * 2,
                       Wph + m * C_ + kk + ck * 8);
        }
        // B: 32 n x 32 k, hi + lo = 256 chunks
        {
            int arr = tid >> 7;
            int c   = tid & 127;
            int n = c >> 2, ck = c & 3;
            const __half* src = (arr ? bgl : bgh) + (size_t)(n0 + n) * C_ + kk + ck * 8;
            cp_async16(sb + (arr ? PL_BL : PL_BH) * 2 + (n * 40 + ck * 8) * 2, src);
        }
        asm volatile("cp.async.commit_group;" ::: "memory");
    };

    load_tile(0, 0);

    const int NKT = C_ / 32;
    for (int kt = 0; kt < NKT; kt++) {
        if (kt + 1 < NKT) {
            load_tile(kt + 1, (kt + 1) & 1);
            asm volatile("cp.async.wait_group 1;" ::: "memory");
        } else {
            asm volatile("cp.async.wait_group 0;" ::: "memory");
        }
        __syncthreads();

        const unsigned sb = smem_base + (kt & 1) * (PL_STAGE * 2);

        unsigned bhf[4][4], blf[4][4];
        #pragma unroll
        for (int ni = 0; ni < 4; ni++) {
            unsigned off = ((ni * 8 + brow) * 40 + bcol8) * 2;
            ldmatrix_x4(bhf[ni][0], bhf[ni][1], bhf[ni][2], bhf[ni][3],
                        sb + PL_BH * 2 + off);
            ldmatrix_x4(blf[ni][0], blf[ni][1], blf[ni][2], blf[ni][3],
                        sb + PL_BL * 2 + off);
        }

        #pragma unroll
        for (int kb = 0; kb < 2; kb++) {
            unsigned ah[2][4];
            #pragma unroll
            for (int mi = 0; mi < 2; mi++) {
                unsigned off = ((wm + mi * 16 + arow) * 40 + kb * 16 + acol8) * 2;
                ldmatrix_x4(ah[mi][0], ah[mi][1], ah[mi][2], ah[mi][3],
                            sb + PL_A * 2 + off);
            }
            #pragma unroll
            for (int ni = 0; ni < 4; ni++) {
                unsigned b0h = bhf[ni][2*kb], b1h = bhf[ni][2*kb+1];
                unsigned b0l = blf[ni][2*kb], b1l = blf[ni][2*kb+1];
                #pragma unroll
                for (int mi = 0; mi < 2; mi++) {
                    mma_f16(acc[mi][ni], ah[mi][0], ah[mi][1], ah[mi][2], ah[mi][3], b0h, b1h);
                    mma_f16(acc[mi][ni], ah[mi][0], ah[mi][1], ah[mi][2], ah[mi][3], b0l, b1l);
                }
            }
        }
        __syncthreads();
    }

    // Stage Y = acc + bias + x into smem fp32 [256][33]
    float* Ys = (float*)smh;
    const float* xb = x + b * (C_ * N_);
    #pragma unroll
    for (int mi = 0; mi < 2; mi++) {
        int o = wm + mi * 16 + g;
        float bv0 = bias[o], bv1 = bias[o + 8];
        #pragma unroll
        for (int ni = 0; ni < 4; ni++) {
            int col = ni * 8 + 2 * q;
            float2 x0 = *(const float2*)&xb[o * N_ + n0 + col];
            float2 x1 = *(const float2*)&xb[(o + 8) * N_ + n0 + col];
            Ys[o * 33 + col]           = acc[mi][ni][0] + bv0 + x0.x;
            Ys[o * 33 + col + 1]       = acc[mi][ni][1] + bv0 + x0.y;
            Ys[(o + 8) * 33 + col]     = acc[mi][ni][2] + bv1 + x1.x;
            Ys[(o + 8) * 33 + col + 1] = acc[mi][ni][3] + bv1 + x1.y;
        }
    }
    __syncthreads();

    // In-CTA LayerNorm over 256 channels for 32 n-cols.
    float* red = (float*)smh + PL_RED_F;   // ssum[8][32], ssq[8][32], smu[32], srstd[32]
    float* ssum = red;
    float* ssq  = red + 256;
    float* smu  = red + 512;
    float* srstd = red + 544;

    const int nc = tid & 31;
    const int cg = tid >> 5;
    {
        float sum = 0.f, sq = 0.f;
        #pragma unroll 8
        for (int i = 0; i < 32; i++) {
            float v = Ys[(cg * 32 + i) * 33 + nc];
            sum += v; sq += v * v;
        }
        ssum[cg * 32 + nc] = sum;
        ssq[cg * 32 + nc]  = sq;
    }
    __syncthreads();
    if (cg == 0) {
        float s = 0.f, qq = 0.f;
        #pragma unroll
        for (int j = 0; j < 8; j++) { s += ssum[j * 32 + nc]; qq += ssq[j * 32 + nc]; }
        float mu = s * (1.f / C_);
        float var = qq * (1.f / C_) - mu * mu;
        smu[nc] = mu;
        srstd[nc] = rsqrtf(var + 1e-5f);
    }
    __syncthreads();
    {
        float mu = smu[nc], rs = srstd[nc];
        float* ob = out + b * (C_ * N_) + n0 + nc;
        #pragma unroll 8
        for (int i = 0; i < 32; i++) {
            int c = cg * 32 + i;
            float v = Ys[c * 33 + nc];
            ob[c * N_] = (v - mu) * rs * ln_g[c] + ln_b[c];
        }
    }
}

// ---------------------------------------------------------------------------
extern "C" void kernel_launch(void* const* d_in, const int* in_sizes, int n_in,
                              void* d_out, int out_size)
{
    const float* x      = (const float*)d_in[0];
    const float* w_qkv  = (const float*)d_in[1];
    const float* b_qkv  = (const float*)d_in[2];
    const float* w_proj = (const float*)d_in[3];
    const float* b_proj = (const float*)d_in[4];
    const float* ln_g   = (const float*)d_in[5];
    const float* ln_b   = (const float*)d_in[6];
    float* out = (float*)d_out;

    const int gemm_smem = 2 * 10240 * 2;    // 40960 B
    const int attn_smem = ATTN_SMEM_H * 2;  // 39424 B
    cudaFuncSetAttribute(qkv_gemm_kernel,
                         cudaFuncAttributeMaxDynamicSharedMemorySize, gemm_smem);
    cudaFuncSetAttribute(attn_kernel,
                         cudaFuncAttributeMaxDynamicSharedMemorySize, attn_smem);
    cudaFuncSetAttribute(proj_ln_kernel,
                         cudaFuncAttributeMaxDynamicSharedMemorySize, PL_SMEM_BYTES);

    __half *p_Wqh, *p_Wph, *p_Xh, *p_Xl, *p_AOh, *p_AOl;
    cudaGetSymbolAddress((void**)&p_Wqh, g_Wqh);
    cudaGetSymbolAddress((void**)&p_Wph, g_Wph);
    cudaGetSymbolAddress((void**)&p_Xh,  g_Xh);
    cudaGetSymbolAddress((void**)&p_Xl,  g_Xl);
    cudaGetSymbolAddress((void**)&p_AOh, g_AOh);
    cudaGetSymbolAddress((void**)&p_AOl, g_AOl);

    prep_w_kernel<<<(WQ_SZ + WP_SZ) / 256, 256>>>(w_qkv, w_proj);
    prep_x_kernel<<<dim3(N_ / 128, C_ / 32, B_), 256>>>(x);
    qkv_gemm_kernel<<<dim3(N_ / 64, (3 * C_) / 128, B_), 256, gemm_smem>>>(
        p_Wqh, p_Xh, p_Xl, b_qkv);
    attn_kernel<<<dim3(N_ / 128, B_ * H_), 128, attn_smem>>>();
    proj_ln_kernel<<<dim3(N_ / 32, B_), 256, PL_SMEM_BYTES>>>(
        p_Wph, p_AOh, p_AOl, b_proj, x, ln_g, ln_b, out);
}

// round 17
// speedup vs baseline: 1.2804x; 1.1436x over previous
#include <cuda_runtime.h>
#include <cuda_fp16.h>

#define B_ 4
#define C_ 256
#define N_ 2048
#define H_ 8
#define D_ 32

// Scratch (allocation-free rule: __device__ globals)
__device__ __half g_Qb[B_*C_*N_];    // [bh][n][d] fp16, pre-scaled by D^-0.5*log2e
__device__ __half g_Kb[B_*C_*N_];    // [bh][n][d] fp16
__device__ __half g_Vb[B_*C_*N_];    // [bh][d][n] fp16
__device__ __half g_Xh[B_*N_*C_];    // x transposed [b][n][c] fp16
__device__ __half g_AOh[B_*N_*C_];   // attention out [b][n][c] fp16
__device__ __half g_Wqh[3*C_*C_];    // QKV weights fp16
__device__ __half g_Wph[C_*C_];      // proj weights fp16

// fp16 inputs, fp32 accumulator
__device__ __forceinline__ void mma_f16(float* d, unsigned a0, unsigned a1,
                                        unsigned a2, unsigned a3,
                                        unsigned b0, unsigned b1) {
    asm volatile(
        "mma.sync.aligned.m16n8k16.row.col.f32.f16.f16.f32 "
        "{%0,%1,%2,%3}, {%4,%5,%6,%7}, {%8,%9}, {%0,%1,%2,%3};\n"
        : "+f"(d[0]), "+f"(d[1]), "+f"(d[2]), "+f"(d[3])
        : "r"(a0), "r"(a1), "r"(a2), "r"(a3), "r"(b0), "r"(b1));
}

// fp16 inputs, fp16 accumulator; D packed {c0,c1},{c2,c3}
__device__ __forceinline__ void mma_f16acc(unsigned& d0, unsigned& d1,
                                           unsigned a0, unsigned a1,
                                           unsigned a2, unsigned a3,
                                           unsigned b0, unsigned b1) {
    asm volatile(
        "mma.sync.aligned.m16n8k16.row.col.f16.f16.f16.f16 "
        "{%0,%1}, {%2,%3,%4,%5}, {%6,%7}, {%0,%1};\n"
        : "+r"(d0), "+r"(d1)
        : "r"(a0), "r"(a1), "r"(a2), "r"(a3), "r"(b0), "r"(b1));
}

__device__ __forceinline__ void ldmatrix_x4(unsigned& r0, unsigned& r1,
                                            unsigned& r2, unsigned& r3,
                                            unsigned addr) {
    asm volatile("ldmatrix.sync.aligned.m8n8.x4.shared.b16 {%0,%1,%2,%3}, [%4];"
                 : "=r"(r0), "=r"(r1), "=r"(r2), "=r"(r3) : "r"(addr));
}

__device__ __forceinline__ void cp_async16(unsigned dst, const void* src) {
    asm volatile("cp.async.cg.shared.global [%0], [%1], 16;"
                 :: "r"(dst), "l"(src));
}
// packs {lo, hi} into f16x2 (lo -> lower 16 bits)
__device__ __forceinline__ unsigned cvt_f16x2(float hi, float lo) {
    unsigned r;
    asm("cvt.rn.f16x2.f32 %0, %1, %2;" : "=r"(r) : "f"(hi), "f"(lo));
    return r;
}
// elementwise 2^x on an f16x2 pair
__device__ __forceinline__ unsigned ex2_f16x2(unsigned x) {
    unsigned r;
    asm("ex2.approx.f16x2 %0, %1;" : "=r"(r) : "r"(x));
    return r;
}
// elementwise f16x2 add
__device__ __forceinline__ unsigned hadd2(unsigned a, unsigned b) {
    unsigned r;
    asm("add.rn.f16x2 %0, %1, %2;" : "=r"(r) : "r"(a), "r"(b));
    return r;
}

// ---------------------------------------------------------------------------
// Prep 1: weights -> fp16.
// ---------------------------------------------------------------------------
#define WQ_SZ (3*C_*C_)
#define WP_SZ (C_*C_)
__global__ __launch_bounds__(256) void prep_w_kernel(
    const float* __restrict__ w_qkv, const float* __restrict__ w_proj)
{
    int i = blockIdx.x * 256 + threadIdx.x;
    if (i < WQ_SZ) g_Wqh[i] = __float2half_rn(w_qkv[i]);
    else           g_Wph[i - WQ_SZ] = __float2half_rn(w_proj[i - WQ_SZ]);
}

// ---------------------------------------------------------------------------
// Prep 2: transpose x: [b][c][n] fp32 -> [b][n][c] fp16 (hi only).
// ---------------------------------------------------------------------------
__global__ __launch_bounds__(256) void prep_x_kernel(const float* __restrict__ x)
{
    __shared__ float ts[32][132];
    const int b  = blockIdx.z;
    const int c0 = blockIdx.y * 32;
    const int n0 = blockIdx.x * 128;
    const int t  = threadIdx.x;

    {
        int cc = t >> 3, nseg = t & 7;
        const float* src = x + b * (C_ * N_) + (c0 + cc) * N_ + n0 + nseg * 16;
        #pragma unroll
        for (int j = 0; j < 4; j++) {
            float4 v = *(const float4*)(src + j * 4);
            int nn = nseg * 16 + j * 4;
            ts[cc][nn] = v.x; ts[cc][nn+1] = v.y; ts[cc][nn+2] = v.z; ts[cc][nn+3] = v.w;
        }
    }
    __syncthreads();
    {
        int nn = t & 127, half = t >> 7;   // half: channels [0,16) or [16,32)
        unsigned w[8];
        #pragma unroll
        for (int j = 0; j < 8; j++) {
            int cc = half * 16 + j * 2;
            w[j] = cvt_f16x2(ts[cc + 1][nn], ts[cc][nn]);
        }
        __half* dst = g_Xh + b * (N_ * C_) + (size_t)(n0 + nn) * C_ + c0 + half * 16;
        uint4* d4 = (uint4*)dst;
        d4[0] = make_uint4(w[0], w[1], w[2], w[3]);
        d4[1] = make_uint4(w[4], w[5], w[6], w[7]);
    }
}

// ---------------------------------------------------------------------------
// QKV GEMM (1-term fp16): CTA 128x64, BK=32, double-buffered cp.async,
// ldmatrix frags. fp16 Q/K [bh][n][d], V [bh][d][n].
// smem: double-buffer 2*7680 halves = 30720 B; epilogue Ts[64][133] fp32
// = 34028 B -> allocate 34304 B.
// ---------------------------------------------------------------------------
#define QG_BH 5120
#define QG_STAGE 7680
#define QG_SMEM_BYTES 34304

__global__ __launch_bounds__(256) void qkv_gemm_kernel(
    const __half* __restrict__ Agh,
    const __half* __restrict__ Bgh,
    const float* __restrict__ bias)
{
    extern __shared__ __half smh[];
    const unsigned smem_base = (unsigned)__cvta_generic_to_shared(smh);

    const int b  = blockIdx.z;
    const int o0 = blockIdx.y * 128;
    const int n0 = blockIdx.x * 64;
    const int tid  = threadIdx.x;
    const int warp = tid >> 5;
    const int lane = tid & 31;
    const int g = lane >> 2;
    const int q = lane & 3;
    const int wm = (warp >> 1) * 32;
    const int wn = (warp & 1) * 32;
    const int arow  = lane & 15;
    const int acol8 = (lane >> 4) * 8;
    const int brow  = lane & 7;
    const int bcol8 = (lane >> 3) * 8;

    const __half* bgh = Bgh + (size_t)b * (N_ * C_);

    float acc[2][4][4] = {};

    auto load_tile = [&](int kt, int s) {
        const int kk = kt * 32;
        const unsigned sb = smem_base + s * (QG_STAGE * 2);
        // A: 128 rows x 32 halves = 512 chunks (2 per thread)
        #pragma unroll
        for (int i = 0; i < 2; i++) {
            int c = tid + i * 256;
            int m = c >> 2, ck = c & 3;
            cp_async16(sb + (m * 40 + ck * 8) * 2, Agh + (o0 + m) * C_ + kk + ck * 8);
        }
        // B: 64 rows x 32 halves = 256 chunks (1 per thread)
        {
            int n = tid >> 2, ck = tid & 3;
            cp_async16(sb + QG_BH * 2 + (n * 40 + ck * 8) * 2,
                       bgh + (size_t)(n0 + n) * C_ + kk + ck * 8);
        }
        asm volatile("cp.async.commit_group;" ::: "memory");
    };

    load_tile(0, 0);

    const int NKT = C_ / 32;
    for (int kt = 0; kt < NKT; kt++) {
        if (kt + 1 < NKT) {
            load_tile(kt + 1, (kt + 1) & 1);
            asm volatile("cp.async.wait_group 1;" ::: "memory");
        } else {
            asm volatile("cp.async.wait_group 0;" ::: "memory");
        }
        __syncthreads();

        const unsigned sb = smem_base + (kt & 1) * (QG_STAGE * 2);

        unsigned bhf[4][4];
        #pragma unroll
        for (int ni = 0; ni < 4; ni++) {
            unsigned off = ((wn + ni * 8 + brow) * 40 + bcol8) * 2;
            ldmatrix_x4(bhf[ni][0], bhf[ni][1], bhf[ni][2], bhf[ni][3],
                        sb + QG_BH * 2 + off);
        }

        #pragma unroll
        for (int kb = 0; kb < 2; kb++) {
            unsigned ah[2][4];
            #pragma unroll
            for (int mi = 0; mi < 2; mi++) {
                unsigned off = ((wm + mi * 16 + arow) * 40 + kb * 16 + acol8) * 2;
                ldmatrix_x4(ah[mi][0], ah[mi][1], ah[mi][2], ah[mi][3], sb + off);
            }
            #pragma unroll
            for (int ni = 0; ni < 4; ni++) {
                #pragma unroll
                for (int mi = 0; mi < 2; mi++) {
                    mma_f16(acc[mi][ni], ah[mi][0], ah[mi][1], ah[mi][2], ah[mi][3],
                            bhf[ni][2*kb], bhf[ni][2*kb+1]);
                }
            }
        }
        __syncthreads();
    }

    const int s = o0 >> 8;                      // 0=q, 1=k, 2=v
    const float scale = (s == 0)
        ? 0.17677669529663687f * 1.4426950408889634f : 1.0f;
    if (s == 2) {
        #pragma unroll
        for (int mi = 0; mi < 2; mi++) {
            int o = o0 + wm + mi * 16 + g;
            float bv0 = bias[o], bv1 = bias[o + 8];
            int cd0 = o & 255, cd1 = (o + 8) & 255;
            #pragma unroll
            for (int ni = 0; ni < 4; ni++) {
                int col = n0 + wn + ni * 8 + 2 * q;
                unsigned p0 = cvt_f16x2(acc[mi][ni][1] + bv0, acc[mi][ni][0] + bv0);
                unsigned p1 = cvt_f16x2(acc[mi][ni][3] + bv1, acc[mi][ni][2] + bv1);
                *(unsigned*)&g_Vb[(size_t)(b * 256 + cd0) * N_ + col] = p0;
                *(unsigned*)&g_Vb[(size_t)(b * 256 + cd1) * N_ + col] = p1;
            }
        }
    } else {
        float* Ts = (float*)smh;   // [64 cols][133] fp32 transpose scratch
        #pragma unroll
        for (int mi = 0; mi < 2; mi++) {
            int r0 = wm + mi * 16 + g;
            int o  = o0 + r0;
            float bv0 = bias[o], bv1 = bias[o + 8];
            #pragma unroll
            for (int ni = 0; ni < 4; ni++) {
                int cl = wn + ni * 8 + 2 * q;
                Ts[cl * 133 + r0]           = (acc[mi][ni][0] + bv0) * scale;
                Ts[(cl + 1) * 133 + r0]     = (acc[mi][ni][1] + bv0) * scale;
                Ts[cl * 133 + r0 + 8]       = (acc[mi][ni][2] + bv1) * scale;
                Ts[(cl + 1) * 133 + r0 + 8] = (acc[mi][ni][3] + bv1) * scale;
            }
        }
        __syncthreads();
        int nl = tid & 63, hh = tid >> 6;
        int h0 = (o0 & 255) >> 5;
        int bh = b * 8 + h0 + hh;
        unsigned w[16];
        const float* row = Ts + nl * 133 + hh * 32;
        #pragma unroll
        for (int dd = 0; dd < 32; dd += 2)
            w[dd >> 1] = cvt_f16x2(row[dd + 1], row[dd]);
        __half* dst = (s == 0 ? g_Qb : g_Kb) + ((size_t)bh * N_ + n0 + nl) * 32;
        uint4* d4 = (uint4*)dst;
        #pragma unroll
        for (int j = 0; j < 4; j++)
            d4[j] = make_uint4(w[j*4], w[j*4+1], w[j*4+2], w[j*4+3]);
    }
}

// ---------------------------------------------------------------------------
// Flash attention, fp16. CTA = 128 queries of one (b,h), 4 warps x 32 rows.
// QK on f16-accum mma; D-fragments feed ex2.approx.f16x2 directly; results
// are PV A-fragments. l via kj-pre-summed fragments + one ones-mma per mi.
// 3-stage cp.async pipeline, one barrier per tile. No running max.
// ---------------------------------------------------------------------------
#define AQ_H 5120                          // Qs[128][40]
#define STG_H 4864                         // 2560 (Ks[64][40]) + 2304 (Vt[32][72])
#define ATTN_SMEM_H (AQ_H + 3*STG_H)       // 19712 halves = 39424 B
#define ONES_F16X2 0x3C003C00u

__global__ __launch_bounds__(128) void attn_kernel()
{
    extern __shared__ __half smh[];
    const unsigned smem_base = (unsigned)__cvta_generic_to_shared(smh);

    const int bh   = blockIdx.y;
    const int n0   = blockIdx.x * 128;
    const int tid  = threadIdx.x;
    const int warp = tid >> 5;
    const int lane = tid & 31;
    const int g    = lane >> 2;
    const int q    = lane & 3;
    const int lrow = lane & 7;
    const int lcol8 = (lane >> 3) * 8;

    const __half* Qg = g_Qb + (size_t)bh * N_ * 32;
    const __half* Kg = g_Kb + (size_t)bh * N_ * 32;
    const __half* Vg = g_Vb + (size_t)bh * 32 * N_;

    auto load_kv = [&](int t, int s) {
        const unsigned sb = smem_base + (AQ_H + s * STG_H) * 2;
        #pragma unroll
        for (int i = 0; i < 2; i++) {
            int c = tid + i * 128;
            int j = c >> 2, off = (c & 3) * 8;
            cp_async16(sb + (j * 40 + off) * 2, Kg + (size_t)(t + j) * 32 + off);
        }
        #pragma unroll
        for (int i = 0; i < 2; i++) {
            int c = tid + i * 128;
            int dd = c >> 3, joff = (c & 7) * 8;
            cp_async16(sb + (2560 + dd * 72 + joff) * 2, Vg + (size_t)dd * N_ + t + joff);
        }
        asm volatile("cp.async.commit_group;" ::: "memory");
    };

    #pragma unroll
    for (int i = 0; i < 4; i++) {
        int c = tid + i * 128;
        int n = c >> 2, off = (c & 3) * 8;
        cp_async16(smem_base + (n * 40 + off) * 2, Qg + (size_t)(n0 + n) * 32 + off);
    }
    load_kv(0, 0);
    load_kv(64, 1);
    asm volatile("cp.async.wait_group 1;" ::: "memory");
    __syncthreads();

    unsigned qa[2][2][4];
    {
        int arow = lane & 15, acol8q = (lane >> 4) * 8;
        #pragma unroll
        for (int mi = 0; mi < 2; mi++) {
            #pragma unroll
            for (int kb = 0; kb < 2; kb++) {
                unsigned off = ((warp * 32 + mi * 16 + arow) * 40 + kb * 16 + acol8q) * 2;
                ldmatrix_x4(qa[mi][kb][0], qa[mi][kb][1], qa[mi][kb][2], qa[mi][kb][3],
                            smem_base + off);
            }
        }
    }

    float o[2][4][4] = {};
    float lac[2][4] = {};

    const int NT = N_ / 64;  // 32
    int st = 0, ldst = 2;
    for (int t = 0; t < NT; t++) {
        if (t + 1 < NT) {
            asm volatile("cp.async.wait_group 1;" ::: "memory");
        } else {
            asm volatile("cp.async.wait_group 0;" ::: "memory");
        }
        __syncthreads();
        if (t + 2 < NT) load_kv((t + 2) * 64, ldst);

        const unsigned ks_u32 = smem_base + (AQ_H + st * STG_H) * 2;
        const unsigned vt_u32 = ks_u32 + 2560 * 2;

        unsigned su[2][8][2] = {};
        #pragma unroll
        for (int ni = 0; ni < 8; ni++) {
            unsigned kf0, kf1, kf2, kf3;
            ldmatrix_x4(kf0, kf1, kf2, kf3,
                        ks_u32 + ((ni * 8 + lrow) * 40 + lcol8) * 2);
            #pragma unroll
            for (int mi = 0; mi < 2; mi++) {
                mma_f16acc(su[mi][ni][0], su[mi][ni][1],
                           qa[mi][0][0], qa[mi][0][1], qa[mi][0][2], qa[mi][0][3],
                           kf0, kf1);
                mma_f16acc(su[mi][ni][0], su[mi][ni][1],
                           qa[mi][1][0], qa[mi][1][1], qa[mi][1][2], qa[mi][1][3],
                           kf2, kf3);
            }
        }

        unsigned pu[2][8][2];
        #pragma unroll
        for (int mi = 0; mi < 2; mi++) {
            #pragma unroll
            for (int ni = 0; ni < 8; ni++) {
                pu[mi][ni][0] = ex2_f16x2(su[mi][ni][0]);
                pu[mi][ni][1] = ex2_f16x2(su[mi][ni][1]);
            }
        }

        #pragma unroll
        for (int ni = 0; ni < 4; ni++) {
            unsigned vf[8];
            unsigned va = vt_u32 + ((ni * 8 + lrow) * 72 + lcol8) * 2;
            ldmatrix_x4(vf[0], vf[1], vf[2], vf[3], va);
            ldmatrix_x4(vf[4], vf[5], vf[6], vf[7], va + 64);
            #pragma unroll
            for (int kj = 0; kj < 4; kj++) {
                #pragma unroll
                for (int mi = 0; mi < 2; mi++) {
                    mma_f16(o[mi][ni],
                            pu[mi][2*kj][0], pu[mi][2*kj][1],
                            pu[mi][2*kj+1][0], pu[mi][2*kj+1][1],
                            vf[2*kj], vf[2*kj+1]);
                }
            }
        }
        #pragma unroll
        for (int mi = 0; mi < 2; mi++) {
            unsigned s0 = hadd2(hadd2(pu[mi][0][0], pu[mi][2][0]),
                                hadd2(pu[mi][4][0], pu[mi][6][0]));
            unsigned s1 = hadd2(hadd2(pu[mi][0][1], pu[mi][2][1]),
                                hadd2(pu[mi][4][1], pu[mi][6][1]));
            unsigned s2 = hadd2(hadd2(pu[mi][1][0], pu[mi][3][0]),
                                hadd2(pu[mi][5][0], pu[mi][7][0]));
            unsigned s3 = hadd2(hadd2(pu[mi][1][1], pu[mi][3][1]),
                                hadd2(pu[mi][5][1], pu[mi][7][1]));
            mma_f16(lac[mi], s0, s1, s2, s3, ONES_F16X2, ONES_F16X2);
        }

        if (++st == 3) st = 0;
        if (++ldst == 3) ldst = 0;
    }

    float linv[4];
    linv[0] = 1.f / lac[0][0];
    linv[1] = 1.f / lac[0][2];
    linv[2] = 1.f / lac[1][0];
    linv[3] = 1.f / lac[1][2];

    __syncthreads();
    float* Os = (float*)smh;  // [128][33]
    #pragma unroll
    for (int mi = 0; mi < 2; mi++) {
        int r = warp * 32 + mi * 16 + g;
        #pragma unroll
        for (int ni = 0; ni < 4; ni++) {
            int dcol = ni * 8 + 2 * q;
            Os[r * 33 + dcol]           = o[mi][ni][0] * linv[mi * 2];
            Os[r * 33 + dcol + 1]       = o[mi][ni][1] * linv[mi * 2];
            Os[(r + 8) * 33 + dcol]     = o[mi][ni][2] * linv[mi * 2 + 1];
            Os[(r + 8) * 33 + dcol + 1] = o[mi][ni][3] * linv[mi * 2 + 1];
        }
    }
    __syncthreads();
    {
        int b = bh >> 3, h = bh & 7;
        unsigned hw[16];
        #pragma unroll
        for (int dd = 0; dd < 32; dd += 2) {
            hw[dd >> 1] = cvt_f16x2(Os[tid * 33 + dd + 1], Os[tid * 33 + dd]);
        }
        size_t base = (size_t)b * (N_ * C_) + (size_t)(n0 + tid) * C_ + h * 32;
        uint4* dh = (uint4*)(g_AOh + base);
        #pragma unroll
        for (int j = 0; j < 4; j++)
            dh[j] = make_uint4(hw[j*4], hw[j*4+1], hw[j*4+2], hw[j*4+3]);
    }
}

// ---------------------------------------------------------------------------
// Fused proj GEMM (1-term) + bias + residual + LayerNorm -> out.
// CTA: M=256 (ALL channels), N=32 n-cols, K=256, BK=32, 256 threads.
// ---------------------------------------------------------------------------
#define PL_BH 10240
#define PL_STAGE 11520                       // halves
#define PL_SMEM_BYTES (2 * PL_STAGE * 2)     // 46080 B
#define PL_RED_F 8704                        // float offset for reduce scratch

__global__ __launch_bounds__(256) void proj_ln_kernel(
    const __half* __restrict__ Wph,
    const __half* __restrict__ AOh,
    const float* __restrict__ bias, const float* __restrict__ x,
    const float* __restrict__ ln_g, const float* __restrict__ ln_b,
    float* __restrict__ out)
{
    extern __shared__ __half smh[];
    const unsigned smem_base = (unsigned)__cvta_generic_to_shared(smh);

    const int b  = blockIdx.y;
    const int n0 = blockIdx.x * 32;
    const int tid  = threadIdx.x;
    const int warp = tid >> 5;
    const int lane = tid & 31;
    const int g = lane >> 2;
    const int q = lane & 3;
    const int wm = warp * 32;
    const int arow  = lane & 15;
    const int acol8 = (lane >> 4) * 8;
    const int brow  = lane & 7;
    const int bcol8 = (lane >> 3) * 8;

    const __half* bgh = AOh + (size_t)b * (N_ * C_);

    float acc[2][4][4] = {};

    auto load_tile = [&](int kt, int s) {
        const int kk = kt * 32;
        const unsigned sb = smem_base + s * (PL_STAGE * 2);
        // A: 256 rows x 32 halves = 1024 chunks (4 per thread)
        #pragma unroll
        for (int i = 0; i < 4; i++) {
            int c = tid + i * 256;
            int m = c >> 2, ck = c & 3;
            cp_async16(sb + (m * 40 + ck * 8) * 2, Wph + m * C_ + kk + ck * 8);
        }
        // B: 32 rows x 32 halves = 128 chunks
        if (tid < 128) {
            int n = tid >> 2, ck = tid & 3;
            cp_async16(sb + PL_BH * 2 + (n * 40 + ck * 8) * 2,
                       bgh + (size_t)(n0 + n) * C_ + kk + ck * 8);
        }
        asm volatile("cp.async.commit_group;" ::: "memory");
    };

    load_tile(0, 0);

    const int NKT = C_ / 32;
    for (int kt = 0; kt < NKT; kt++) {
        if (kt + 1 < NKT) {
            load_tile(kt + 1, (kt + 1) & 1);
            asm volatile("cp.async.wait_group 1;" ::: "memory");
        } else {
            asm volatile("cp.async.wait_group 0;" ::: "memory");
        }
        __syncthreads();

        const unsigned sb = smem_base + (kt & 1) * (PL_STAGE * 2);

        unsigned bhf[4][4];
        #pragma unroll
        for (int ni = 0; ni < 4; ni++) {
            unsigned off = ((ni * 8 + brow) * 40 + bcol8) * 2;
            ldmatrix_x4(bhf[ni][0], bhf[ni][1], bhf[ni][2], bhf[ni][3],
                        sb + PL_BH * 2 + off);
        }

        #pragma unroll
        for (int kb = 0; kb < 2; kb++) {
            unsigned ah[2][4];
            #pragma unroll
            for (int mi = 0; mi < 2; mi++) {
                unsigned off = ((wm + mi * 16 + arow) * 40 + kb * 16 + acol8) * 2;
                ldmatrix_x4(ah[mi][0], ah[mi][1], ah[mi][2], ah[mi][3], sb + off);
            }
            #pragma unroll
            for (int ni = 0; ni < 4; ni++) {
                #pragma unroll
                for (int mi = 0; mi < 2; mi++) {
                    mma_f16(acc[mi][ni], ah[mi][0], ah[mi][1], ah[mi][2], ah[mi][3],
                            bhf[ni][2*kb], bhf[ni][2*kb+1]);
                }
            }
        }
        __syncthreads();
    }

    // Stage Y = acc + bias + x into smem fp32 [256][33]
    float* Ys = (float*)smh;
    const float* xb = x + b * (C_ * N_);
    #pragma unroll
    for (int mi = 0; mi < 2; mi++) {
        int o = wm + mi * 16 + g;
        float bv0 = bias[o], bv1 = bias[o + 8];
        #pragma unroll
        for (int ni = 0; ni < 4; ni++) {
            int col = ni * 8 + 2 * q;
            float2 x0 = *(const float2*)&xb[o * N_ + n0 + col];
            float2 x1 = *(const float2*)&xb[(o + 8) * N_ + n0 + col];
            Ys[o * 33 + col]           = acc[mi][ni][0] + bv0 + x0.x;
            Ys[o * 33 + col + 1]       = acc[mi][ni][1] + bv0 + x0.y;
            Ys[(o + 8) * 33 + col]     = acc[mi][ni][2] + bv1 + x1.x;
            Ys[(o + 8) * 33 + col + 1] = acc[mi][ni][3] + bv1 + x1.y;
        }
    }
    __syncthreads();

    // In-CTA LayerNorm over 256 channels for 32 n-cols.
    float* red = (float*)smh + PL_RED_F;
    float* ssum = red;
    float* ssq  = red + 256;
    float* smu  = red + 512;
    float* srstd = red + 544;

    const int nc = tid & 31;
    const int cg = tid >> 5;
    {
        float sum = 0.f, sq = 0.f;
        #pragma unroll 8
        for (int i = 0; i < 32; i++) {
            float v = Ys[(cg * 32 + i) * 33 + nc];
            sum += v; sq += v * v;
        }
        ssum[cg * 32 + nc] = sum;
        ssq[cg * 32 + nc]  = sq;
    }
    __syncthreads();
    if (cg == 0) {
        float s = 0.f, qq = 0.f;
        #pragma unroll
        for (int j = 0; j < 8; j++) { s += ssum[j * 32 + nc]; qq += ssq[j * 32 + nc]; }
        float mu = s * (1.f / C_);
        float var = qq * (1.f / C_) - mu * mu;
        smu[nc] = mu;
        srstd[nc] = rsqrtf(var + 1e-5f);
    }
    __syncthreads();
    {
        float mu = smu[nc], rs = srstd[nc];
        float* ob = out + b * (C_ * N_) + n0 + nc;
        #pragma unroll 8
        for (int i = 0; i < 32; i++) {
            int c = cg * 32 + i;
            float v = Ys[c * 33 + nc];
            ob[c * N_] = (v - mu) * rs * ln_g[c] + ln_b[c];
        }
    }
}

// ---------------------------------------------------------------------------
extern "C" void kernel_launch(void* const* d_in, const int* in_sizes, int n_in,
                              void* d_out, int out_size)
{
    const float* x      = (const float*)d_in[0];
    const float* w_qkv  = (const float*)d_in[1];
    const float* b_qkv  = (const float*)d_in[2];
    const float* w_proj = (const float*)d_in[3];
    const float* b_proj = (const float*)d_in[4];
    const float* ln_g   = (const float*)d_in[5];
    const float* ln_b   = (const float*)d_in[6];
    float* out = (float*)d_out;

    const int attn_smem = ATTN_SMEM_H * 2;  // 39424 B
    cudaFuncSetAttribute(qkv_gemm_kernel,
                         cudaFuncAttributeMaxDynamicSharedMemorySize, QG_SMEM_BYTES);
    cudaFuncSetAttribute(attn_kernel,
                         cudaFuncAttributeMaxDynamicSharedMemorySize, attn_smem);
    cudaFuncSetAttribute(proj_ln_kernel,
                         cudaFuncAttributeMaxDynamicSharedMemorySize, PL_SMEM_BYTES);

    __half *p_Wqh, *p_Wph, *p_Xh, *p_AOh;
    cudaGetSymbolAddress((void**)&p_Wqh, g_Wqh);
    cudaGetSymbolAddress((void**)&p_Wph, g_Wph);
    cudaGetSymbolAddress((void**)&p_Xh,  g_Xh);
    cudaGetSymbolAddress((void**)&p_AOh, g_AOh);

    prep_w_kernel<<<(WQ_SZ + WP_SZ) / 256, 256>>>(w_qkv, w_proj);
    prep_x_kernel<<<dim3(N_ / 128, C_ / 32, B_), 256>>>(x);
    qkv_gemm_kernel<<<dim3(N_ / 64, (3 * C_) / 128, B_), 256, QG_SMEM_BYTES>>>(
        p_Wqh, p_Xh, b_qkv);
    attn_kernel<<<dim3(N_ / 128, B_ * H_), 128, attn_smem>>>();
    proj_ln_kernel<<<dim3(N_ / 32, B_), 256, PL_SMEM_BYTES>>>(
        p_Wph, p_AOh, b_proj, x, ln_g, ln_b, out);
}